// round 1
// baseline (speedup 1.0000x reference)
#include <cuda_runtime.h>
#include <cuda_bf16.h>
#include <math.h>

#define NMAX 100000
#define EMAX 1600000
#define DH   128
#define DOUT 64

// GCN2Conv constants
#define ALPHA_C  0.2f
#define BETA1_C  0.6931471805599453f   /* ln(2)   */
#define BETA2_C  0.4054651081081644f   /* ln(1.5) */

// ---------------- static device scratch (allocation-free rule) ----------------
__device__ float g_h0[NMAX * DH];
__device__ float g_f [NMAX * DH];   // reused: f1 then f2
__device__ float g_x1[NMAX * DH];
__device__ int   g_deg_out[NMAX];
__device__ int   g_deg_in [NMAX];
__device__ float g_rs_out[NMAX];
__device__ float g_rs_in [NMAX];
__device__ int   g_row_ptr[NMAX + 1];
__device__ int   g_cursor [NMAX];
__device__ int   g_cols   [EMAX];
__device__ float g_Wp1[DH * DH];    // (1-b1)I + b1*cw1
__device__ float g_Wf [DH * DOUT];  // W2' @ w2
__device__ float g_bf [DOUT];       // cb2 @ w2 + b2

// ---------------- setup kernels ----------------
__global__ void zero_deg_kernel(int n) {
    int i = blockIdx.x * blockDim.x + threadIdx.x;
    if (i < n) { g_deg_out[i] = 0; g_deg_in[i] = 0; }
}

__global__ void deg_kernel(const int* __restrict__ src, const int* __restrict__ dst, int E) {
    int e = blockIdx.x * blockDim.x + threadIdx.x;
    if (e < E) {
        atomicAdd(&g_deg_out[src[e]], 1);
        atomicAdd(&g_deg_in [dst[e]], 1);
    }
}

__global__ void rs_kernel(int n) {
    int i = blockIdx.x * blockDim.x + threadIdx.x;
    if (i < n) {
        g_rs_out[i] = rsqrtf(fmaxf((float)g_deg_out[i], 1.0f));
        g_rs_in [i] = rsqrtf(fmaxf((float)g_deg_in [i], 1.0f));
    }
}

// single-block exclusive scan of deg_in -> row_ptr (+ cursor copy)
__global__ void scan_kernel(int n) {
    __shared__ int part[1024];
    __shared__ int total_sh;
    int t = threadIdx.x;
    int C = (n + 1023) >> 10;
    int lo = t * C;
    int hi = lo + C; if (hi > n) hi = n;
    int s = 0;
    for (int i = lo; i < hi; i++) s += g_deg_in[i];
    part[t] = s;
    __syncthreads();
    if (t == 0) {
        int run = 0;
        for (int i = 0; i < 1024; i++) { int v = part[i]; part[i] = run; run += v; }
        total_sh = run;
    }
    __syncthreads();
    int off = part[t];
    for (int i = lo; i < hi; i++) {
        g_row_ptr[i] = off;
        g_cursor [i] = off;
        off += g_deg_in[i];
    }
    if (t == 0) g_row_ptr[n] = total_sh;
}

__global__ void fill_kernel(const int* __restrict__ src, const int* __restrict__ dst, int E) {
    int e = blockIdx.x * blockDim.x + threadIdx.x;
    if (e < E) {
        int p = atomicAdd(&g_cursor[dst[e]], 1);
        g_cols[p] = src[e];
    }
}

// W1' = beta1*cw1 + (1-beta1)*I        <<<128,128>>>
__global__ void make_wp1_kernel(const float* __restrict__ cw1) {
    int k = blockIdx.x, j = threadIdx.x;
    float v = BETA1_C * cw1[k * DH + j];
    if (k == j) v += (1.0f - BETA1_C);
    g_Wp1[k * DH + j] = v;
}

// Wf = (beta2*cw2 + (1-beta2)I) @ w2 ;  bf = cb2 @ w2 + b2    <<<128,64>>>
__global__ void make_wf_kernel(const float* __restrict__ cw2, const float* __restrict__ w2,
                               const float* __restrict__ cb2, const float* __restrict__ b2) {
    int k = blockIdx.x, j = threadIdx.x;
    float s = 0.0f;
    for (int m = 0; m < DH; m++) s += cw2[k * DH + m] * w2[m * DOUT + j];
    g_Wf[k * DOUT + j] = BETA2_C * s + (1.0f - BETA2_C) * w2[k * DOUT + j];
    if (k == 0) {
        float t = 0.0f;
        for (int m = 0; m < DH; m++) t += cb2[m] * w2[m * DOUT + j];
        g_bf[j] = t + b2[j];
    }
}

// ---------------- SpMM + residual fusion ----------------
// f[i] = 0.8 * rs_in[i] * sum_{s in N(i)} x[s]*rs_out[s]  +  0.2 * x0[i]
// one warp per dst row; lane owns a float4 column slice
__global__ void __launch_bounds__(256) spmm_kernel(const float* __restrict__ x,
                                                   const float* __restrict__ x0,
                                                   float* __restrict__ f, int n) {
    int w    = (blockIdx.x * blockDim.x + threadIdx.x) >> 5;
    int lane = threadIdx.x & 31;
    if (w >= n) return;
    int start = g_row_ptr[w];
    int end   = g_row_ptr[w + 1];
    float4 acc = make_float4(0.f, 0.f, 0.f, 0.f);
    for (int j = start; j < end; j += 32) {
        int cnt = end - j; if (cnt > 32) cnt = 32;
        int   c  = 0;
        float sw = 0.0f;
        if (lane < cnt) { c = g_cols[j + lane]; sw = g_rs_out[c]; }
        for (int t = 0; t < cnt; t++) {
            int   cc = __shfl_sync(0xffffffffu, c,  t);
            float ww = __shfl_sync(0xffffffffu, sw, t);
            float4 v = *(const float4*)(x + (size_t)cc * DH + lane * 4);
            acc.x = fmaf(v.x, ww, acc.x);
            acc.y = fmaf(v.y, ww, acc.y);
            acc.z = fmaf(v.z, ww, acc.z);
            acc.w = fmaf(v.w, ww, acc.w);
        }
    }
    float ri = g_rs_in[w] * (1.0f - ALPHA_C);
    float4 xv = *(const float4*)(x0 + (size_t)w * DH + lane * 4);
    float4 o;
    o.x = fmaf(acc.x, ri, ALPHA_C * xv.x);
    o.y = fmaf(acc.y, ri, ALPHA_C * xv.y);
    o.z = fmaf(acc.z, ri, ALPHA_C * xv.z);
    o.w = fmaf(acc.w, ri, ALPHA_C * xv.w);
    *(float4*)(f + (size_t)w * DH + lane * 4) = o;
}

// ---------------- GEMM: C[n,NC] = A[n,128] @ B[128,NC] + bias (opt relu) ----------------
// 64-row tile, 256 threads, A tile in smem, B streamed through L1 (hot, reused by all blocks)
template <int NC, bool RELU>
__global__ void __launch_bounds__(256) gemm_kernel(const float* __restrict__ A,
                                                   const float* __restrict__ B,
                                                   const float* __restrict__ bias,
                                                   float* __restrict__ C, int n) {
    constexpr int CG  = NC / 4;         // float4 column groups (32 or 16)
    constexpr int RPT = 64 * CG / 256;  // rows per thread (8 or 4)
    __shared__ float As[64 * DH];

    int m0  = blockIdx.x * 64;
    int tid = threadIdx.x;

    // load A tile (64x128) as float4, guarded
    const float4* A4  = (const float4*)A;
    float4*       As4 = (float4*)As;
    size_t base4 = (size_t)m0 * (DH / 4);
#pragma unroll
    for (int i = 0; i < 8; i++) {
        int idx = tid + i * 256;       // 0..2047
        int row = idx >> 5;            // /32 float4 per row
        if (m0 + row < n) As4[idx] = A4[base4 + idx];
        else              As4[idx] = make_float4(0.f, 0.f, 0.f, 0.f);
    }
    __syncthreads();

    int c_id = tid % CG;
    int r_id = tid / CG;

    float4 acc[RPT];
#pragma unroll
    for (int i = 0; i < RPT; i++) acc[i] = make_float4(0.f, 0.f, 0.f, 0.f);

    const float4* B4 = (const float4*)B;
#pragma unroll 4
    for (int k = 0; k < DH; k += 4) {
        float4 b0 = __ldg(&B4[(k + 0) * CG + c_id]);
        float4 b1 = __ldg(&B4[(k + 1) * CG + c_id]);
        float4 b2 = __ldg(&B4[(k + 2) * CG + c_id]);
        float4 b3 = __ldg(&B4[(k + 3) * CG + c_id]);
#pragma unroll
        for (int i = 0; i < RPT; i++) {
            float4 a = *(const float4*)&As[(r_id * RPT + i) * DH + k];
            acc[i].x = fmaf(a.x, b0.x, fmaf(a.y, b1.x, fmaf(a.z, b2.x, fmaf(a.w, b3.x, acc[i].x))));
            acc[i].y = fmaf(a.x, b0.y, fmaf(a.y, b1.y, fmaf(a.z, b2.y, fmaf(a.w, b3.y, acc[i].y))));
            acc[i].z = fmaf(a.x, b0.z, fmaf(a.y, b1.z, fmaf(a.z, b2.z, fmaf(a.w, b3.z, acc[i].z))));
            acc[i].w = fmaf(a.x, b0.w, fmaf(a.y, b1.w, fmaf(a.z, b2.w, fmaf(a.w, b3.w, acc[i].w))));
        }
    }

    float4 bv = __ldg(&((const float4*)bias)[c_id]);
#pragma unroll
    for (int i = 0; i < RPT; i++) {
        int row = m0 + r_id * RPT + i;
        if (row < n) {
            float4 o;
            o.x = acc[i].x + bv.x;
            o.y = acc[i].y + bv.y;
            o.z = acc[i].z + bv.z;
            o.w = acc[i].w + bv.w;
            if (RELU) {
                o.x = fmaxf(o.x, 0.f); o.y = fmaxf(o.y, 0.f);
                o.z = fmaxf(o.z, 0.f); o.w = fmaxf(o.w, 0.f);
            }
            *(float4*)(C + (size_t)row * NC + c_id * 4) = o;
        }
    }
}

// ---------------- launch ----------------
extern "C" void kernel_launch(void* const* d_in, const int* in_sizes, int n_in,
                              void* d_out, int out_size) {
    const float* feat = (const float*)d_in[0];
    const int*   src  = (const int*)  d_in[1];
    const int*   dst  = (const int*)  d_in[2];
    const float* w1   = (const float*)d_in[3];
    const float* b1   = (const float*)d_in[4];
    const float* cw1  = (const float*)d_in[5];
    const float* cb1  = (const float*)d_in[6];
    const float* cw2  = (const float*)d_in[7];
    const float* cb2  = (const float*)d_in[8];
    const float* w2   = (const float*)d_in[9];
    const float* b2   = (const float*)d_in[10];
    float* out = (float*)d_out;

    int n = in_sizes[0] / DH;   // 100000
    int E = in_sizes[1];        // 1600000

    void *p_h0, *p_f, *p_x1, *p_wp1, *p_wf, *p_bf;
    cudaGetSymbolAddress(&p_h0,  g_h0);
    cudaGetSymbolAddress(&p_f,   g_f);
    cudaGetSymbolAddress(&p_x1,  g_x1);
    cudaGetSymbolAddress(&p_wp1, g_Wp1);
    cudaGetSymbolAddress(&p_wf,  g_Wf);
    cudaGetSymbolAddress(&p_bf,  g_bf);

    int nb  = (n + 255) / 256;
    int eb  = (E + 255) / 256;
    int gb  = (n + 63) / 64;           // gemm blocks (64-row tiles)
    int sb  = (n * 32 + 255) / 256;    // spmm blocks (warp per row)

    // graph preprocessing (shared by both conv layers)
    zero_deg_kernel<<<nb, 256>>>(n);
    deg_kernel<<<eb, 256>>>(src, dst, E);
    rs_kernel<<<nb, 256>>>(n);
    scan_kernel<<<1, 1024>>>(n);
    fill_kernel<<<eb, 256>>>(src, dst, E);

    // fold identity-mapped linears into single weight matrices
    make_wp1_kernel<<<DH, DH>>>(cw1);
    make_wf_kernel<<<DH, DOUT>>>(cw2, w2, cb2, b2);

    // fc1: h0 = relu(feat @ w1 + b1)
    gemm_kernel<DH, true><<<gb, 256>>>(feat, w1, b1, (float*)p_h0, n);

    // conv1 SpMM + residual -> f1
    spmm_kernel<<<sb, 256>>>((const float*)p_h0, (const float*)p_h0, (float*)p_f, n);

    // conv1 linear: x1 = relu(f1 @ W1' + cb1)
    gemm_kernel<DH, true><<<gb, 256>>>((const float*)p_f, (const float*)p_wp1, cb1, (float*)p_x1, n);

    // conv2 SpMM + residual -> f2
    spmm_kernel<<<sb, 256>>>((const float*)p_x1, (const float*)p_h0, (float*)p_f, n);

    // conv2 linear fused with fc2: out = f2 @ Wf + bf
    gemm_kernel<DOUT, false><<<gb, 256>>>((const float*)p_f, (const float*)p_wf, (const float*)p_bf, out, n);
}

// round 2
// speedup vs baseline: 1.3693x; 1.3693x over previous
#include <cuda_runtime.h>
#include <cuda_bf16.h>
#include <math.h>

#define NMAX 100000
#define EMAX 1600000
#define DH   128
#define DOUT 64
#define NBLK_MAX ((NMAX + 255) / 256)   /* 391 */

// GCN2Conv constants
#define ALPHA_C  0.2f
#define BETA1_C  0.6931471805599453f   /* ln(2)   */
#define BETA2_C  0.4054651081081644f   /* ln(1.5) */

// ---------------- static device scratch (allocation-free rule) ----------------
__device__ float g_h0[NMAX * DH];
__device__ float g_f [NMAX * DH];   // reused: f1 then f2
__device__ float g_x1[NMAX * DH];
__device__ int   g_deg_out[NMAX];
__device__ int   g_deg_in [NMAX];
__device__ float g_rs_out[NMAX];
__device__ float g_rs_in [NMAX];
__device__ int   g_row_ptr[NMAX + 1];
__device__ int   g_cursor [NMAX];
__device__ int   g_cols   [EMAX];
__device__ int   g_blk_sums[NBLK_MAX + 1];
__device__ float g_Wp1[DH * DH];    // (1-b1)I + b1*cw1
__device__ float g_Wf [DH * DOUT];  // W2' @ w2
__device__ float g_bf [DOUT];       // cb2 @ w2 + b2

// ---------------- setup kernels ----------------
__global__ void zero_deg_kernel(int n) {
    int i = blockIdx.x * blockDim.x + threadIdx.x;
    if (i < n) { g_deg_out[i] = 0; g_deg_in[i] = 0; }
}

__global__ void deg_kernel(const int* __restrict__ src, const int* __restrict__ dst, int E) {
    int e = blockIdx.x * blockDim.x + threadIdx.x;
    if (e < E) {
        atomicAdd(&g_deg_out[src[e]], 1);
        atomicAdd(&g_deg_in [dst[e]], 1);
    }
}

__global__ void rs_kernel(int n) {
    int i = blockIdx.x * blockDim.x + threadIdx.x;
    if (i < n) {
        g_rs_out[i] = rsqrtf(fmaxf((float)g_deg_out[i], 1.0f));
        g_rs_in [i] = rsqrtf(fmaxf((float)g_deg_in [i], 1.0f));
    }
}

// ---- parallel scan, 3 stages ----
// stage 1: per-block sums of deg_in
__global__ void blocksum_kernel(int n) {
    __shared__ int warp_s[8];
    int i = blockIdx.x * 256 + threadIdx.x;
    int v = (i < n) ? g_deg_in[i] : 0;
#pragma unroll
    for (int o = 16; o > 0; o >>= 1) v += __shfl_down_sync(0xffffffffu, v, o);
    if ((threadIdx.x & 31) == 0) warp_s[threadIdx.x >> 5] = v;
    __syncthreads();
    if (threadIdx.x < 8) {
        int s = warp_s[threadIdx.x];
#pragma unroll
        for (int o = 4; o > 0; o >>= 1) s += __shfl_down_sync(0xffu, s, o);
        if (threadIdx.x == 0) g_blk_sums[blockIdx.x] = s;
    }
}

// stage 2: single-block exclusive scan of nblk (<512) block sums
__global__ void scan_sums_kernel(int nblk, int n) {
    __shared__ int sh[512];
    int t = threadIdx.x;
    sh[t] = (t < nblk) ? g_blk_sums[t] : 0;
    __syncthreads();
    // Hillis-Steele inclusive
#pragma unroll
    for (int o = 1; o < 512; o <<= 1) {
        int v = (t >= o) ? sh[t - o] : 0;
        __syncthreads();
        sh[t] += v;
        __syncthreads();
    }
    // write exclusive
    if (t < nblk) g_blk_sums[t] = (t == 0) ? 0 : sh[t - 1];
    if (t == 0) {
        g_blk_sums[nblk] = sh[511];
        g_row_ptr[n]     = sh[511];
    }
}

// stage 3: intra-block exclusive scan + block offset -> row_ptr, cursor
__global__ void writeptr_kernel(int n) {
    __shared__ int sh[256];
    int t = threadIdx.x;
    int i = blockIdx.x * 256 + t;
    int v = (i < n) ? g_deg_in[i] : 0;
    sh[t] = v;
    __syncthreads();
#pragma unroll
    for (int o = 1; o < 256; o <<= 1) {
        int u = (t >= o) ? sh[t - o] : 0;
        __syncthreads();
        sh[t] += u;
        __syncthreads();
    }
    if (i < n) {
        int off = g_blk_sums[blockIdx.x] + sh[t] - v;  // exclusive
        g_row_ptr[i] = off;
        g_cursor [i] = off;
    }
}

__global__ void fill_kernel(const int* __restrict__ src, const int* __restrict__ dst, int E) {
    int e = blockIdx.x * blockDim.x + threadIdx.x;
    if (e < E) {
        int p = atomicAdd(&g_cursor[dst[e]], 1);
        g_cols[p] = src[e];
    }
}

// W1' = beta1*cw1 + (1-beta1)*I        <<<128,128>>>
__global__ void make_wp1_kernel(const float* __restrict__ cw1) {
    int k = blockIdx.x, j = threadIdx.x;
    float v = BETA1_C * cw1[k * DH + j];
    if (k == j) v += (1.0f - BETA1_C);
    g_Wp1[k * DH + j] = v;
}

// Wf = (beta2*cw2 + (1-beta2)I) @ w2 ;  bf = cb2 @ w2 + b2    <<<128,64>>>
__global__ void make_wf_kernel(const float* __restrict__ cw2, const float* __restrict__ w2,
                               const float* __restrict__ cb2, const float* __restrict__ b2) {
    int k = blockIdx.x, j = threadIdx.x;
    float s = 0.0f;
    for (int m = 0; m < DH; m++) s += cw2[k * DH + m] * w2[m * DOUT + j];
    g_Wf[k * DOUT + j] = BETA2_C * s + (1.0f - BETA2_C) * w2[k * DOUT + j];
    if (k == 0) {
        float t = 0.0f;
        for (int m = 0; m < DH; m++) t += cb2[m] * w2[m * DOUT + j];
        g_bf[j] = t + b2[j];
    }
}

// ---------------- SpMM + residual fusion ----------------
// f[i] = 0.8 * rs_in[i] * sum_{s in N(i)} x[s]*rs_out[s]  +  0.2 * x0[i]
// one warp per dst row; lane owns a float4 column slice
__global__ void __launch_bounds__(256) spmm_kernel(const float* __restrict__ x,
                                                   const float* __restrict__ x0,
                                                   float* __restrict__ f, int n) {
    int w    = (blockIdx.x * blockDim.x + threadIdx.x) >> 5;
    int lane = threadIdx.x & 31;
    if (w >= n) return;
    int start = g_row_ptr[w];
    int end   = g_row_ptr[w + 1];
    float4 acc = make_float4(0.f, 0.f, 0.f, 0.f);
    for (int j = start; j < end; j += 32) {
        int cnt = end - j; if (cnt > 32) cnt = 32;
        int   c  = 0;
        float sw = 0.0f;
        if (lane < cnt) { c = g_cols[j + lane]; sw = g_rs_out[c]; }
        for (int t = 0; t < cnt; t++) {
            int   cc = __shfl_sync(0xffffffffu, c,  t);
            float ww = __shfl_sync(0xffffffffu, sw, t);
            float4 v = *(const float4*)(x + (size_t)cc * DH + lane * 4);
            acc.x = fmaf(v.x, ww, acc.x);
            acc.y = fmaf(v.y, ww, acc.y);
            acc.z = fmaf(v.z, ww, acc.z);
            acc.w = fmaf(v.w, ww, acc.w);
        }
    }
    float ri = g_rs_in[w] * (1.0f - ALPHA_C);
    float4 xv = *(const float4*)(x0 + (size_t)w * DH + lane * 4);
    float4 o;
    o.x = fmaf(acc.x, ri, ALPHA_C * xv.x);
    o.y = fmaf(acc.y, ri, ALPHA_C * xv.y);
    o.z = fmaf(acc.z, ri, ALPHA_C * xv.z);
    o.w = fmaf(acc.w, ri, ALPHA_C * xv.w);
    *(float4*)(f + (size_t)w * DH + lane * 4) = o;
}

// ---------------- GEMM: C[n,NC] = A[n,128] @ B[128,NC] + bias (opt relu) ----------------
template <int NC, bool RELU>
__global__ void __launch_bounds__(256) gemm_kernel(const float* __restrict__ A,
                                                   const float* __restrict__ B,
                                                   const float* __restrict__ bias,
                                                   float* __restrict__ C, int n) {
    constexpr int CG  = NC / 4;         // float4 column groups (32 or 16)
    constexpr int RPT = 64 * CG / 256;  // rows per thread (8 or 4)
    __shared__ float As[64 * DH];

    int m0  = blockIdx.x * 64;
    int tid = threadIdx.x;

    // load A tile (64x128) as float4, guarded
    const float4* A4  = (const float4*)A;
    float4*       As4 = (float4*)As;
    size_t base4 = (size_t)m0 * (DH / 4);
#pragma unroll
    for (int i = 0; i < 8; i++) {
        int idx = tid + i * 256;       // 0..2047
        int row = idx >> 5;            // /32 float4 per row
        if (m0 + row < n) As4[idx] = A4[base4 + idx];
        else              As4[idx] = make_float4(0.f, 0.f, 0.f, 0.f);
    }
    __syncthreads();

    int c_id = tid % CG;
    int r_id = tid / CG;

    float4 acc[RPT];
#pragma unroll
    for (int i = 0; i < RPT; i++) acc[i] = make_float4(0.f, 0.f, 0.f, 0.f);

    const float4* B4 = (const float4*)B;
#pragma unroll 4
    for (int k = 0; k < DH; k += 4) {
        float4 b0 = __ldg(&B4[(k + 0) * CG + c_id]);
        float4 b1 = __ldg(&B4[(k + 1) * CG + c_id]);
        float4 b2 = __ldg(&B4[(k + 2) * CG + c_id]);
        float4 b3 = __ldg(&B4[(k + 3) * CG + c_id]);
#pragma unroll
        for (int i = 0; i < RPT; i++) {
            float4 a = *(const float4*)&As[(r_id * RPT + i) * DH + k];
            acc[i].x = fmaf(a.x, b0.x, fmaf(a.y, b1.x, fmaf(a.z, b2.x, fmaf(a.w, b3.x, acc[i].x))));
            acc[i].y = fmaf(a.x, b0.y, fmaf(a.y, b1.y, fmaf(a.z, b2.y, fmaf(a.w, b3.y, acc[i].y))));
            acc[i].z = fmaf(a.x, b0.z, fmaf(a.y, b1.z, fmaf(a.z, b2.z, fmaf(a.w, b3.z, acc[i].z))));
            acc[i].w = fmaf(a.x, b0.w, fmaf(a.y, b1.w, fmaf(a.z, b2.w, fmaf(a.w, b3.w, acc[i].w))));
        }
    }

    float4 bv = __ldg(&((const float4*)bias)[c_id]);
#pragma unroll
    for (int i = 0; i < RPT; i++) {
        int row = m0 + r_id * RPT + i;
        if (row < n) {
            float4 o;
            o.x = acc[i].x + bv.x;
            o.y = acc[i].y + bv.y;
            o.z = acc[i].z + bv.z;
            o.w = acc[i].w + bv.w;
            if (RELU) {
                o.x = fmaxf(o.x, 0.f); o.y = fmaxf(o.y, 0.f);
                o.z = fmaxf(o.z, 0.f); o.w = fmaxf(o.w, 0.f);
            }
            *(float4*)(C + (size_t)row * NC + c_id * 4) = o;
        }
    }
}

// ---------------- launch ----------------
extern "C" void kernel_launch(void* const* d_in, const int* in_sizes, int n_in,
                              void* d_out, int out_size) {
    const float* feat = (const float*)d_in[0];
    const int*   src  = (const int*)  d_in[1];
    const int*   dst  = (const int*)  d_in[2];
    const float* w1   = (const float*)d_in[3];
    const float* b1   = (const float*)d_in[4];
    const float* cw1  = (const float*)d_in[5];
    const float* cb1  = (const float*)d_in[6];
    const float* cw2  = (const float*)d_in[7];
    const float* cb2  = (const float*)d_in[8];
    const float* w2   = (const float*)d_in[9];
    const float* b2   = (const float*)d_in[10];
    float* out = (float*)d_out;

    int n = in_sizes[0] / DH;   // 100000
    int E = in_sizes[1];        // 1600000

    void *p_h0, *p_f, *p_x1, *p_wp1, *p_wf, *p_bf;
    cudaGetSymbolAddress(&p_h0,  g_h0);
    cudaGetSymbolAddress(&p_f,   g_f);
    cudaGetSymbolAddress(&p_x1,  g_x1);
    cudaGetSymbolAddress(&p_wp1, g_Wp1);
    cudaGetSymbolAddress(&p_wf,  g_Wf);
    cudaGetSymbolAddress(&p_bf,  g_bf);

    int nb   = (n + 255) / 256;
    int eb   = (E + 255) / 256;
    int gb   = (n + 63) / 64;           // gemm blocks (64-row tiles)
    int sb   = (n * 32 + 255) / 256;    // spmm blocks (warp per row)
    int nblk = (n + 255) / 256;         // scan blocks

    // graph preprocessing (shared by both conv layers)
    zero_deg_kernel<<<nb, 256>>>(n);
    deg_kernel<<<eb, 256>>>(src, dst, E);
    rs_kernel<<<nb, 256>>>(n);
    blocksum_kernel<<<nblk, 256>>>(n);
    scan_sums_kernel<<<1, 512>>>(nblk, n);
    writeptr_kernel<<<nblk, 256>>>(n);
    fill_kernel<<<eb, 256>>>(src, dst, E);

    // fold identity-mapped linears into single weight matrices
    make_wp1_kernel<<<DH, DH>>>(cw1);
    make_wf_kernel<<<DH, DOUT>>>(cw2, w2, cb2, b2);

    // fc1: h0 = relu(feat @ w1 + b1)
    gemm_kernel<DH, true><<<gb, 256>>>(feat, w1, b1, (float*)p_h0, n);

    // conv1 SpMM + residual -> f1
    spmm_kernel<<<sb, 256>>>((const float*)p_h0, (const float*)p_h0, (float*)p_f, n);

    // conv1 linear: x1 = relu(f1 @ W1' + cb1)
    gemm_kernel<DH, true><<<gb, 256>>>((const float*)p_f, (const float*)p_wp1, cb1, (float*)p_x1, n);

    // conv2 SpMM + residual -> f2
    spmm_kernel<<<sb, 256>>>((const float*)p_x1, (const float*)p_h0, (float*)p_f, n);

    // conv2 linear fused with fc2: out = f2 @ Wf + bf
    gemm_kernel<DOUT, false><<<gb, 256>>>((const float*)p_f, (const float*)p_wf, (const float*)p_bf, out, n);
}

// round 3
// speedup vs baseline: 1.3755x; 1.0045x over previous
#include <cuda_runtime.h>
#include <cuda_bf16.h>
#include <math.h>
#include <stdint.h>

#define NMAX 100000
#define EMAX 1600000
#define DH   128
#define DOUT 64
#define NBLK_MAX ((NMAX + 255) / 256)   /* 391 */

// GCN2Conv constants
#define ALPHA_C  0.2f
#define BETA1_C  0.6931471805599453f   /* ln(2)   */
#define BETA2_C  0.4054651081081644f   /* ln(1.5) */

// ---------------- static device scratch (allocation-free rule) ----------------
__device__ float g_h0[NMAX * DH];
__device__ float g_f [NMAX * DH];   // reused: f1 then f2
__device__ float g_x1[NMAX * DH];
__device__ int   g_deg_out[NMAX];
__device__ int   g_deg_in [NMAX];
__device__ float g_rs_out[NMAX];
__device__ float g_rs_in [NMAX];
__device__ int   g_row_ptr[NMAX + 1];
__device__ int   g_cursor [NMAX];
__device__ int   g_cols   [EMAX];
__device__ int   g_blk_sums[NBLK_MAX + 1];
// tf32 hi/lo split weight matrices (fp32 bit patterns with tf32 mantissa)
__device__ float g_w1hi [DH * DH];
__device__ float g_w1lo [DH * DH];
__device__ float g_wp1hi[DH * DH];
__device__ float g_wp1lo[DH * DH];
__device__ float g_wfhi [DH * DOUT];
__device__ float g_wflo [DH * DOUT];
__device__ float g_bf   [DOUT];     // cb2 @ w2 + b2

// ---------------- tf32 helpers ----------------
__device__ __forceinline__ uint32_t cvt_tf32(float v) {
    uint32_t r;
    asm("cvt.rna.tf32.f32 %0, %1;" : "=r"(r) : "f"(v));
    return r;
}
__device__ __forceinline__ void tf32_split(float v, float& hi, float& lo) {
    uint32_t h = cvt_tf32(v);
    hi = __uint_as_float(h);
    lo = __uint_as_float(cvt_tf32(v - hi));
}
__device__ __forceinline__ void mma8(float* c, const uint32_t* a, uint32_t b0, uint32_t b1) {
    asm("mma.sync.aligned.m16n8k8.row.col.f32.tf32.tf32.f32 "
        "{%0,%1,%2,%3}, {%4,%5,%6,%7}, {%8,%9}, {%0,%1,%2,%3};"
        : "+f"(c[0]), "+f"(c[1]), "+f"(c[2]), "+f"(c[3])
        : "r"(a[0]), "r"(a[1]), "r"(a[2]), "r"(a[3]), "r"(b0), "r"(b1));
}

// ---------------- setup kernels ----------------
__global__ void zero_deg_kernel(int n) {
    int i = blockIdx.x * blockDim.x + threadIdx.x;
    if (i < n) { g_deg_out[i] = 0; g_deg_in[i] = 0; }
}

__global__ void deg_kernel(const int* __restrict__ src, const int* __restrict__ dst, int E) {
    int e = blockIdx.x * blockDim.x + threadIdx.x;
    if (e < E) {
        atomicAdd(&g_deg_out[src[e]], 1);
        atomicAdd(&g_deg_in [dst[e]], 1);
    }
}

__global__ void rs_kernel(int n) {
    int i = blockIdx.x * blockDim.x + threadIdx.x;
    if (i < n) {
        g_rs_out[i] = rsqrtf(fmaxf((float)g_deg_out[i], 1.0f));
        g_rs_in [i] = rsqrtf(fmaxf((float)g_deg_in [i], 1.0f));
    }
}

// ---- parallel scan, 3 stages ----
__global__ void blocksum_kernel(int n) {
    __shared__ int warp_s[8];
    int i = blockIdx.x * 256 + threadIdx.x;
    int v = (i < n) ? g_deg_in[i] : 0;
#pragma unroll
    for (int o = 16; o > 0; o >>= 1) v += __shfl_down_sync(0xffffffffu, v, o);
    if ((threadIdx.x & 31) == 0) warp_s[threadIdx.x >> 5] = v;
    __syncthreads();
    if (threadIdx.x < 8) {
        int s = warp_s[threadIdx.x];
#pragma unroll
        for (int o = 4; o > 0; o >>= 1) s += __shfl_down_sync(0xffu, s, o);
        if (threadIdx.x == 0) g_blk_sums[blockIdx.x] = s;
    }
}

__global__ void scan_sums_kernel(int nblk, int n) {
    __shared__ int sh[512];
    int t = threadIdx.x;
    sh[t] = (t < nblk) ? g_blk_sums[t] : 0;
    __syncthreads();
#pragma unroll
    for (int o = 1; o < 512; o <<= 1) {
        int v = (t >= o) ? sh[t - o] : 0;
        __syncthreads();
        sh[t] += v;
        __syncthreads();
    }
    if (t < nblk) g_blk_sums[t] = (t == 0) ? 0 : sh[t - 1];
    if (t == 0) {
        g_blk_sums[nblk] = sh[511];
        g_row_ptr[n]     = sh[511];
    }
}

__global__ void writeptr_kernel(int n) {
    __shared__ int sh[256];
    int t = threadIdx.x;
    int i = blockIdx.x * 256 + t;
    int v = (i < n) ? g_deg_in[i] : 0;
    sh[t] = v;
    __syncthreads();
#pragma unroll
    for (int o = 1; o < 256; o <<= 1) {
        int u = (t >= o) ? sh[t - o] : 0;
        __syncthreads();
        sh[t] += u;
        __syncthreads();
    }
    if (i < n) {
        int off = g_blk_sums[blockIdx.x] + sh[t] - v;  // exclusive
        g_row_ptr[i] = off;
        g_cursor [i] = off;
    }
}

__global__ void fill_kernel(const int* __restrict__ src, const int* __restrict__ dst, int E) {
    int e = blockIdx.x * blockDim.x + threadIdx.x;
    if (e < E) {
        int p = atomicAdd(&g_cursor[dst[e]], 1);
        g_cols[p] = src[e];
    }
}

// split fc1 weight w1 -> hi/lo   <<<128,128>>>
__global__ void split_w1_kernel(const float* __restrict__ w1) {
    int k = blockIdx.x, j = threadIdx.x;
    float hi, lo;
    tf32_split(w1[k * DH + j], hi, lo);
    g_w1hi[k * DH + j] = hi;
    g_w1lo[k * DH + j] = lo;
}

// W1' = beta1*cw1 + (1-beta1)*I  -> hi/lo   <<<128,128>>>
__global__ void make_wp1_kernel(const float* __restrict__ cw1) {
    int k = blockIdx.x, j = threadIdx.x;
    float v = BETA1_C * cw1[k * DH + j];
    if (k == j) v += (1.0f - BETA1_C);
    float hi, lo;
    tf32_split(v, hi, lo);
    g_wp1hi[k * DH + j] = hi;
    g_wp1lo[k * DH + j] = lo;
}

// Wf = (beta2*cw2 + (1-beta2)I) @ w2 -> hi/lo ;  bf = cb2 @ w2 + b2    <<<128,64>>>
__global__ void make_wf_kernel(const float* __restrict__ cw2, const float* __restrict__ w2,
                               const float* __restrict__ cb2, const float* __restrict__ b2) {
    int k = blockIdx.x, j = threadIdx.x;
    float s = 0.0f;
    for (int m = 0; m < DH; m++) s += cw2[k * DH + m] * w2[m * DOUT + j];
    float v = BETA2_C * s + (1.0f - BETA2_C) * w2[k * DOUT + j];
    float hi, lo;
    tf32_split(v, hi, lo);
    g_wfhi[k * DOUT + j] = hi;
    g_wflo[k * DOUT + j] = lo;
    if (k == 0) {
        float t = 0.0f;
        for (int m = 0; m < DH; m++) t += cb2[m] * w2[m * DOUT + j];
        g_bf[j] = t + b2[j];
    }
}

// ---------------- SpMM + residual fusion ----------------
__global__ void __launch_bounds__(256) spmm_kernel(const float* __restrict__ x,
                                                   const float* __restrict__ x0,
                                                   float* __restrict__ f, int n) {
    int w    = (blockIdx.x * blockDim.x + threadIdx.x) >> 5;
    int lane = threadIdx.x & 31;
    if (w >= n) return;
    int start = g_row_ptr[w];
    int end   = g_row_ptr[w + 1];
    float4 acc = make_float4(0.f, 0.f, 0.f, 0.f);
    for (int j = start; j < end; j += 32) {
        int cnt = end - j; if (cnt > 32) cnt = 32;
        int   c  = 0;
        float sw = 0.0f;
        if (lane < cnt) { c = g_cols[j + lane]; sw = g_rs_out[c]; }
        for (int t = 0; t < cnt; t++) {
            int   cc = __shfl_sync(0xffffffffu, c,  t);
            float ww = __shfl_sync(0xffffffffu, sw, t);
            float4 v = *(const float4*)(x + (size_t)cc * DH + lane * 4);
            acc.x = fmaf(v.x, ww, acc.x);
            acc.y = fmaf(v.y, ww, acc.y);
            acc.z = fmaf(v.z, ww, acc.z);
            acc.w = fmaf(v.w, ww, acc.w);
        }
    }
    float ri = g_rs_in[w] * (1.0f - ALPHA_C);
    float4 xv = *(const float4*)(x0 + (size_t)w * DH + lane * 4);
    float4 o;
    o.x = fmaf(acc.x, ri, ALPHA_C * xv.x);
    o.y = fmaf(acc.y, ri, ALPHA_C * xv.y);
    o.z = fmaf(acc.z, ri, ALPHA_C * xv.z);
    o.w = fmaf(acc.w, ri, ALPHA_C * xv.w);
    *(float4*)(f + (size_t)w * DH + lane * 4) = o;
}

// ---------------- tensor-core GEMM (3xTF32): C[n,NC] = A[n,128] @ B[128,NC] + bias ----------------
// block = 64 M-rows, 256 threads (8 warps, 2m x 4n grid)
// warp: 2 m16-tiles x (NC/32) n8-tiles
template <int NC, bool RELU>
__global__ void __launch_bounds__(256) gemm_tc_kernel(const float* __restrict__ A,
                                                      const float* __restrict__ Bhig,
                                                      const float* __restrict__ Blog,
                                                      const float* __restrict__ bias,
                                                      float* __restrict__ C, int n) {
    constexpr int AST = DH + 4;     // 132, conflict-free A frag loads
    constexpr int BST = NC + 8;     // conflict-free B frag loads
    constexpr int NTW = NC / 32;    // n8-tiles per warp (4 or 2)

    extern __shared__ float sm[];
    float* As = sm;                       // 64 x AST
    float* Bh = sm + 64 * AST;            // 128 x BST
    float* Bl = Bh + DH * BST;            // 128 x BST

    int tid = threadIdx.x;
    int m0  = blockIdx.x * 64;

    // stage A tile (64 x 128 fp32)
    {
        const float4* A4 = (const float4*)A;
        size_t base4 = (size_t)m0 * (DH / 4);
#pragma unroll
        for (int i = 0; i < 8; i++) {
            int idx = tid + i * 256;
            int row = idx >> 5;
            int c4  = idx & 31;
            float4 v = (m0 + row < n) ? A4[base4 + idx] : make_float4(0.f, 0.f, 0.f, 0.f);
            *(float4*)&As[row * AST + c4 * 4] = v;
        }
    }
    // stage B hi/lo tiles (128 x NC each)
    {
        const float4* H4 = (const float4*)Bhig;
        const float4* L4 = (const float4*)Blog;
        constexpr int TOT4 = DH * NC / 4;
#pragma unroll
        for (int i = 0; i < TOT4 / 256; i++) {
            int idx = tid + i * 256;
            int row = idx / (NC / 4);
            int c4  = idx % (NC / 4);
            *(float4*)&Bh[row * BST + c4 * 4] = H4[idx];
            *(float4*)&Bl[row * BST + c4 * 4] = L4[idx];
        }
    }
    __syncthreads();

    int warp = tid >> 5, lane = tid & 31;
    int gid  = lane >> 2, tig = lane & 3;
    int wm   = warp & 1;                // m half (rows wm*32 .. +32)
    int wn   = warp >> 1;               // n quarter
    int abase = wm * 32 + gid;
    int nbase = wn * (NC / 4);

    float acc[2][NTW][4];
#pragma unroll
    for (int mt = 0; mt < 2; mt++)
#pragma unroll
        for (int nt = 0; nt < NTW; nt++)
#pragma unroll
            for (int q = 0; q < 4; q++) acc[mt][nt][q] = 0.f;

#pragma unroll 4
    for (int k0 = 0; k0 < DH; k0 += 8) {
        uint32_t ah[2][4], al[2][4];
#pragma unroll
        for (int mt = 0; mt < 2; mt++) {
            int ar = abase + mt * 16;
            float f0 = As[ar * AST + k0 + tig];
            float f1 = As[(ar + 8) * AST + k0 + tig];
            float f2 = As[ar * AST + k0 + 4 + tig];
            float f3 = As[(ar + 8) * AST + k0 + 4 + tig];
            ah[mt][0] = cvt_tf32(f0); al[mt][0] = cvt_tf32(f0 - __uint_as_float(ah[mt][0]));
            ah[mt][1] = cvt_tf32(f1); al[mt][1] = cvt_tf32(f1 - __uint_as_float(ah[mt][1]));
            ah[mt][2] = cvt_tf32(f2); al[mt][2] = cvt_tf32(f2 - __uint_as_float(ah[mt][2]));
            ah[mt][3] = cvt_tf32(f3); al[mt][3] = cvt_tf32(f3 - __uint_as_float(ah[mt][3]));
        }
#pragma unroll
        for (int nt = 0; nt < NTW; nt++) {
            int ncol = nbase + nt * 8 + gid;
            uint32_t bh0 = __float_as_uint(Bh[(k0 + tig) * BST + ncol]);
            uint32_t bh1 = __float_as_uint(Bh[(k0 + 4 + tig) * BST + ncol]);
            uint32_t bl0 = __float_as_uint(Bl[(k0 + tig) * BST + ncol]);
            uint32_t bl1 = __float_as_uint(Bl[(k0 + 4 + tig) * BST + ncol]);
#pragma unroll
            for (int mt = 0; mt < 2; mt++) {
                mma8(acc[mt][nt], ah[mt], bh0, bh1);
                mma8(acc[mt][nt], ah[mt], bl0, bl1);
                mma8(acc[mt][nt], al[mt], bh0, bh1);
            }
        }
    }

    // epilogue
#pragma unroll
    for (int mt = 0; mt < 2; mt++) {
        int r0 = m0 + wm * 32 + mt * 16 + gid;
        int r1 = r0 + 8;
#pragma unroll
        for (int nt = 0; nt < NTW; nt++) {
            int nc0 = nbase + nt * 8 + tig * 2;
            float bv0 = bias[nc0], bv1 = bias[nc0 + 1];
            float v0 = acc[mt][nt][0] + bv0;
            float v1 = acc[mt][nt][1] + bv1;
            float v2 = acc[mt][nt][2] + bv0;
            float v3 = acc[mt][nt][3] + bv1;
            if (RELU) {
                v0 = fmaxf(v0, 0.f); v1 = fmaxf(v1, 0.f);
                v2 = fmaxf(v2, 0.f); v3 = fmaxf(v3, 0.f);
            }
            if (r0 < n) *(float2*)&C[(size_t)r0 * NC + nc0] = make_float2(v0, v1);
            if (r1 < n) *(float2*)&C[(size_t)r1 * NC + nc0] = make_float2(v2, v3);
        }
    }
}

// ---------------- launch ----------------
extern "C" void kernel_launch(void* const* d_in, const int* in_sizes, int n_in,
                              void* d_out, int out_size) {
    const float* feat = (const float*)d_in[0];
    const int*   src  = (const int*)  d_in[1];
    const int*   dst  = (const int*)  d_in[2];
    const float* w1   = (const float*)d_in[3];
    const float* b1   = (const float*)d_in[4];
    const float* cw1  = (const float*)d_in[5];
    const float* cb1  = (const float*)d_in[6];
    const float* cw2  = (const float*)d_in[7];
    const float* cb2  = (const float*)d_in[8];
    const float* w2   = (const float*)d_in[9];
    const float* b2   = (const float*)d_in[10];
    float* out = (float*)d_out;

    int n = in_sizes[0] / DH;   // 100000
    int E = in_sizes[1];        // 1600000

    void *p_h0, *p_f, *p_x1;
    void *p_w1hi, *p_w1lo, *p_wp1hi, *p_wp1lo, *p_wfhi, *p_wflo, *p_bf;
    cudaGetSymbolAddress(&p_h0,    g_h0);
    cudaGetSymbolAddress(&p_f,     g_f);
    cudaGetSymbolAddress(&p_x1,    g_x1);
    cudaGetSymbolAddress(&p_w1hi,  g_w1hi);
    cudaGetSymbolAddress(&p_w1lo,  g_w1lo);
    cudaGetSymbolAddress(&p_wp1hi, g_wp1hi);
    cudaGetSymbolAddress(&p_wp1lo, g_wp1lo);
    cudaGetSymbolAddress(&p_wfhi,  g_wfhi);
    cudaGetSymbolAddress(&p_wflo,  g_wflo);
    cudaGetSymbolAddress(&p_bf,    g_bf);

    // opt-in dynamic smem
    constexpr int SMEM128 = (64 * (DH + 4) + 2 * DH * (128 + 8)) * 4;  // 173056 B
    constexpr int SMEM64  = (64 * (DH + 4) + 2 * DH * (64 + 8)) * 4;   // 107520 B
    cudaFuncSetAttribute(gemm_tc_kernel<128, true>,
                         cudaFuncAttributeMaxDynamicSharedMemorySize, SMEM128);
    cudaFuncSetAttribute(gemm_tc_kernel<64, false>,
                         cudaFuncAttributeMaxDynamicSharedMemorySize, SMEM64);

    int nb   = (n + 255) / 256;
    int eb   = (E + 255) / 256;
    int gb   = (n + 63) / 64;           // gemm blocks (64-row tiles)
    int sb   = (n * 32 + 255) / 256;    // spmm blocks (warp per row)
    int nblk = (n + 255) / 256;         // scan blocks

    // graph preprocessing (shared by both conv layers)
    zero_deg_kernel<<<nb, 256>>>(n);
    deg_kernel<<<eb, 256>>>(src, dst, E);
    rs_kernel<<<nb, 256>>>(n);
    blocksum_kernel<<<nblk, 256>>>(n);
    scan_sums_kernel<<<1, 512>>>(nblk, n);
    writeptr_kernel<<<nblk, 256>>>(n);
    fill_kernel<<<eb, 256>>>(src, dst, E);

    // fold + split weights
    split_w1_kernel<<<DH, DH>>>(w1);
    make_wp1_kernel<<<DH, DH>>>(cw1);
    make_wf_kernel<<<DH, DOUT>>>(cw2, w2, cb2, b2);

    // fc1: h0 = relu(feat @ w1 + b1)
    gemm_tc_kernel<128, true><<<gb, 256, SMEM128>>>(feat, (const float*)p_w1hi,
        (const float*)p_w1lo, b1, (float*)p_h0, n);

    // conv1 SpMM + residual -> f1
    spmm_kernel<<<sb, 256>>>((const float*)p_h0, (const float*)p_h0, (float*)p_f, n);

    // conv1 linear: x1 = relu(f1 @ W1' + cb1)
    gemm_tc_kernel<128, true><<<gb, 256, SMEM128>>>((const float*)p_f, (const float*)p_wp1hi,
        (const float*)p_wp1lo, cb1, (float*)p_x1, n);

    // conv2 SpMM + residual -> f2
    spmm_kernel<<<sb, 256>>>((const float*)p_x1, (const float*)p_h0, (float*)p_f, n);

    // conv2 linear fused with fc2: out = f2 @ Wf + bf
    gemm_tc_kernel<64, false><<<gb, 256, SMEM64>>>((const float*)p_f, (const float*)p_wfhi,
        (const float*)p_wflo, (const float*)p_bf, out, n);
}

// round 4
// speedup vs baseline: 1.3872x; 1.0085x over previous
#include <cuda_runtime.h>
#include <cuda_bf16.h>
#include <math.h>
#include <stdint.h>

#define NMAX 100000
#define EMAX 1600000
#define DH   128
#define DOUT 64
#define NBLK_MAX ((NMAX + 255) / 256)   /* 391 */

// GCN2Conv constants
#define ALPHA_C  0.2f
#define BETA1_C  0.6931471805599453f   /* ln(2)   */
#define BETA2_C  0.4054651081081644f   /* ln(1.5) */

// ---------------- static device scratch (allocation-free rule) ----------------
__device__ float g_h0[NMAX * DH];
__device__ float g_f [NMAX * DH];   // reused: f1 then f2
__device__ float g_x1[NMAX * DH];
__device__ int   g_deg_out[NMAX];
__device__ int   g_deg_in [NMAX];
__device__ float g_rs_out[NMAX];
__device__ float g_rs_in [NMAX];
__device__ int   g_row_ptr[NMAX + 1];
__device__ int   g_cursor [NMAX];
__device__ int   g_cols   [EMAX];
__device__ int   g_blk_sums[NBLK_MAX + 1];
// tf32 hi/lo split weight matrices (fp32 bit patterns with tf32 mantissa)
__device__ float g_w1hi [DH * DH];
__device__ float g_w1lo [DH * DH];
__device__ float g_wp1hi[DH * DH];
__device__ float g_wp1lo[DH * DH];
__device__ float g_wfhi [DH * DOUT];
__device__ float g_wflo [DH * DOUT];
__device__ float g_bf   [DOUT];     // cb2 @ w2 + b2

// ---------------- tf32 helpers ----------------
__device__ __forceinline__ uint32_t cvt_tf32(float v) {
    uint32_t r;
    asm("cvt.rna.tf32.f32 %0, %1;" : "=r"(r) : "f"(v));
    return r;
}
__device__ __forceinline__ void tf32_split(float v, float& hi, float& lo) {
    uint32_t h = cvt_tf32(v);
    hi = __uint_as_float(h);
    lo = __uint_as_float(cvt_tf32(v - hi));
}
__device__ __forceinline__ void mma8(float* c, const uint32_t* a, uint32_t b0, uint32_t b1) {
    asm("mma.sync.aligned.m16n8k8.row.col.f32.tf32.tf32.f32 "
        "{%0,%1,%2,%3}, {%4,%5,%6,%7}, {%8,%9}, {%0,%1,%2,%3};"
        : "+f"(c[0]), "+f"(c[1]), "+f"(c[2]), "+f"(c[3])
        : "r"(a[0]), "r"(a[1]), "r"(a[2]), "r"(a[3]), "r"(b0), "r"(b1));
}

// ---------------- setup kernels ----------------
// merged weight prep: split w1, build+split W1', build+split Wf, bf   <<<128,128>>>
__global__ void prep_weights_kernel(const float* __restrict__ w1,
                                    const float* __restrict__ cw1,
                                    const float* __restrict__ cw2,
                                    const float* __restrict__ w2,
                                    const float* __restrict__ cb2,
                                    const float* __restrict__ b2) {
    int k = blockIdx.x, j = threadIdx.x;
    float hi, lo;
    // fc1 weight split
    tf32_split(w1[k * DH + j], hi, lo);
    g_w1hi[k * DH + j] = hi;
    g_w1lo[k * DH + j] = lo;
    // W1' = beta1*cw1 + (1-beta1)*I
    float v = BETA1_C * cw1[k * DH + j];
    if (k == j) v += (1.0f - BETA1_C);
    tf32_split(v, hi, lo);
    g_wp1hi[k * DH + j] = hi;
    g_wp1lo[k * DH + j] = lo;
    // Wf = (beta2*cw2 + (1-beta2)I) @ w2 ; bf = cb2 @ w2 + b2
    if (j < DOUT) {
        float s = 0.0f;
        for (int m = 0; m < DH; m++) s += cw2[k * DH + m] * w2[m * DOUT + j];
        float vf = BETA2_C * s + (1.0f - BETA2_C) * w2[k * DOUT + j];
        tf32_split(vf, hi, lo);
        g_wfhi[k * DOUT + j] = hi;
        g_wflo[k * DOUT + j] = lo;
        if (k == 0) {
            float t = 0.0f;
            for (int m = 0; m < DH; m++) t += cb2[m] * w2[m * DOUT + j];
            g_bf[j] = t + b2[j];
        }
    }
}

__global__ void zero_deg_kernel(int n) {
    int i = blockIdx.x * blockDim.x + threadIdx.x;
    if (i < n) { g_deg_out[i] = 0; g_deg_in[i] = 0; }
}

__global__ void deg_kernel(const int* __restrict__ src, const int* __restrict__ dst, int E) {
    int e = blockIdx.x * blockDim.x + threadIdx.x;
    if (e < E) {
        atomicAdd(&g_deg_out[src[e]], 1);
        atomicAdd(&g_deg_in [dst[e]], 1);
    }
}

// merged: rsqrt norms + per-block sums of deg_in
__global__ void rs_blocksum_kernel(int n) {
    __shared__ int warp_s[8];
    int i = blockIdx.x * 256 + threadIdx.x;
    int d_in = 0;
    if (i < n) {
        int d_out = g_deg_out[i];
        d_in = g_deg_in[i];
        g_rs_out[i] = rsqrtf(fmaxf((float)d_out, 1.0f));
        g_rs_in [i] = rsqrtf(fmaxf((float)d_in,  1.0f));
    }
    int v = d_in;
#pragma unroll
    for (int o = 16; o > 0; o >>= 1) v += __shfl_down_sync(0xffffffffu, v, o);
    if ((threadIdx.x & 31) == 0) warp_s[threadIdx.x >> 5] = v;
    __syncthreads();
    if (threadIdx.x < 8) {
        int s = warp_s[threadIdx.x];
#pragma unroll
        for (int o = 4; o > 0; o >>= 1) s += __shfl_down_sync(0xffu, s, o);
        if (threadIdx.x == 0) g_blk_sums[blockIdx.x] = s;
    }
}

__global__ void scan_sums_kernel(int nblk, int n) {
    __shared__ int sh[512];
    int t = threadIdx.x;
    sh[t] = (t < nblk) ? g_blk_sums[t] : 0;
    __syncthreads();
#pragma unroll
    for (int o = 1; o < 512; o <<= 1) {
        int v = (t >= o) ? sh[t - o] : 0;
        __syncthreads();
        sh[t] += v;
        __syncthreads();
    }
    if (t < nblk) g_blk_sums[t] = (t == 0) ? 0 : sh[t - 1];
    if (t == 0) {
        g_blk_sums[nblk] = sh[511];
        g_row_ptr[n]     = sh[511];
    }
}

__global__ void writeptr_kernel(int n) {
    __shared__ int sh[256];
    int t = threadIdx.x;
    int i = blockIdx.x * 256 + t;
    int v = (i < n) ? g_deg_in[i] : 0;
    sh[t] = v;
    __syncthreads();
#pragma unroll
    for (int o = 1; o < 256; o <<= 1) {
        int u = (t >= o) ? sh[t - o] : 0;
        __syncthreads();
        sh[t] += u;
        __syncthreads();
    }
    if (i < n) {
        int off = g_blk_sums[blockIdx.x] + sh[t] - v;  // exclusive
        g_row_ptr[i] = off;
        g_cursor [i] = off;
    }
}

__global__ void fill_kernel(const int* __restrict__ src, const int* __restrict__ dst, int E) {
    int e = blockIdx.x * blockDim.x + threadIdx.x;
    if (e < E) {
        int p = atomicAdd(&g_cursor[dst[e]], 1);
        g_cols[p] = src[e];
    }
}

// ---------------- SpMM + residual fusion ----------------
__global__ void __launch_bounds__(256) spmm_kernel(const float* __restrict__ x,
                                                   const float* __restrict__ x0,
                                                   float* __restrict__ f, int n) {
    int w    = (blockIdx.x * blockDim.x + threadIdx.x) >> 5;
    int lane = threadIdx.x & 31;
    if (w >= n) return;
    int start = g_row_ptr[w];
    int end   = g_row_ptr[w + 1];
    float4 acc = make_float4(0.f, 0.f, 0.f, 0.f);
    for (int j = start; j < end; j += 32) {
        int cnt = end - j; if (cnt > 32) cnt = 32;
        int   c  = 0;
        float sw = 0.0f;
        if (lane < cnt) { c = g_cols[j + lane]; sw = g_rs_out[c]; }
        for (int t = 0; t < cnt; t++) {
            int   cc = __shfl_sync(0xffffffffu, c,  t);
            float ww = __shfl_sync(0xffffffffu, sw, t);
            float4 v = *(const float4*)(x + (size_t)cc * DH + lane * 4);
            acc.x = fmaf(v.x, ww, acc.x);
            acc.y = fmaf(v.y, ww, acc.y);
            acc.z = fmaf(v.z, ww, acc.z);
            acc.w = fmaf(v.w, ww, acc.w);
        }
    }
    float ri = g_rs_in[w] * (1.0f - ALPHA_C);
    float4 xv = *(const float4*)(x0 + (size_t)w * DH + lane * 4);
    float4 o;
    o.x = fmaf(acc.x, ri, ALPHA_C * xv.x);
    o.y = fmaf(acc.y, ri, ALPHA_C * xv.y);
    o.z = fmaf(acc.z, ri, ALPHA_C * xv.z);
    o.w = fmaf(acc.w, ri, ALPHA_C * xv.w);
    *(float4*)(f + (size_t)w * DH + lane * 4) = o;
}

// ---------------- tensor-core GEMM (3xTF32): C[n,NC] = A[n,128] @ B[128,NC] + bias ----------------
// block = 128 M-rows, 256 threads (8 warps in 4m x 2n grid)
// warp: 2 m16-tiles x (NC/16) n8-tiles
template <int NC, bool RELU>
__global__ void __launch_bounds__(256) gemm_tc_kernel(const float* __restrict__ A,
                                                      const float* __restrict__ Bhig,
                                                      const float* __restrict__ Blog,
                                                      const float* __restrict__ bias,
                                                      float* __restrict__ C, int n) {
    constexpr int AST = DH + 4;     // 132, conflict-free A frag loads
    constexpr int BST = NC + 8;     // conflict-free B frag loads
    constexpr int NTW = NC / 16;    // n8-tiles per warp (8 or 4)

    extern __shared__ float sm[];
    float* As = sm;                       // 128 x AST
    float* Bh = sm + 128 * AST;           // 128 x BST
    float* Bl = Bh + DH * BST;            // 128 x BST

    int tid = threadIdx.x;
    int m0  = blockIdx.x * 128;

    // stage A tile (128 x 128 fp32)
    {
        const float4* A4 = (const float4*)A;
        size_t base4 = (size_t)m0 * (DH / 4);
#pragma unroll
        for (int i = 0; i < 16; i++) {
            int idx = tid + i * 256;       // 0..4095
            int row = idx >> 5;
            int c4  = idx & 31;
            float4 v = (m0 + row < n) ? A4[base4 + idx] : make_float4(0.f, 0.f, 0.f, 0.f);
            *(float4*)&As[row * AST + c4 * 4] = v;
        }
    }
    // stage B hi/lo tiles (128 x NC each)
    {
        const float4* H4 = (const float4*)Bhig;
        const float4* L4 = (const float4*)Blog;
        constexpr int TOT4 = DH * NC / 4;
#pragma unroll
        for (int i = 0; i < TOT4 / 256; i++) {
            int idx = tid + i * 256;
            int row = idx / (NC / 4);
            int c4  = idx % (NC / 4);
            *(float4*)&Bh[row * BST + c4 * 4] = H4[idx];
            *(float4*)&Bl[row * BST + c4 * 4] = L4[idx];
        }
    }
    __syncthreads();

    int warp = tid >> 5, lane = tid & 31;
    int gid  = lane >> 2, tig = lane & 3;
    int wm   = warp >> 1;               // m quarter (rows wm*32 .. +32)
    int wn   = warp & 1;                // n half
    int abase = wm * 32 + gid;
    int nbase = wn * (NC / 2);

    float acc[2][NTW][4];
#pragma unroll
    for (int mt = 0; mt < 2; mt++)
#pragma unroll
        for (int nt = 0; nt < NTW; nt++)
#pragma unroll
            for (int q = 0; q < 4; q++) acc[mt][nt][q] = 0.f;

#pragma unroll 2
    for (int k0 = 0; k0 < DH; k0 += 8) {
        uint32_t ah[2][4], al[2][4];
#pragma unroll
        for (int mt = 0; mt < 2; mt++) {
            int ar = abase + mt * 16;
            float f0 = As[ar * AST + k0 + tig];
            float f1 = As[(ar + 8) * AST + k0 + tig];
            float f2 = As[ar * AST + k0 + 4 + tig];
            float f3 = As[(ar + 8) * AST + k0 + 4 + tig];
            ah[mt][0] = cvt_tf32(f0); al[mt][0] = cvt_tf32(f0 - __uint_as_float(ah[mt][0]));
            ah[mt][1] = cvt_tf32(f1); al[mt][1] = cvt_tf32(f1 - __uint_as_float(ah[mt][1]));
            ah[mt][2] = cvt_tf32(f2); al[mt][2] = cvt_tf32(f2 - __uint_as_float(ah[mt][2]));
            ah[mt][3] = cvt_tf32(f3); al[mt][3] = cvt_tf32(f3 - __uint_as_float(ah[mt][3]));
        }
#pragma unroll
        for (int nt = 0; nt < NTW; nt++) {
            int ncol = nbase + nt * 8 + gid;
            uint32_t bh0 = __float_as_uint(Bh[(k0 + tig) * BST + ncol]);
            uint32_t bh1 = __float_as_uint(Bh[(k0 + 4 + tig) * BST + ncol]);
            uint32_t bl0 = __float_as_uint(Bl[(k0 + tig) * BST + ncol]);
            uint32_t bl1 = __float_as_uint(Bl[(k0 + 4 + tig) * BST + ncol]);
#pragma unroll
            for (int mt = 0; mt < 2; mt++) {
                mma8(acc[mt][nt], ah[mt], bh0, bh1);
                mma8(acc[mt][nt], ah[mt], bl0, bl1);
                mma8(acc[mt][nt], al[mt], bh0, bh1);
            }
        }
    }

    // epilogue
#pragma unroll
    for (int mt = 0; mt < 2; mt++) {
        int r0 = m0 + wm * 32 + mt * 16 + gid;
        int r1 = r0 + 8;
#pragma unroll
        for (int nt = 0; nt < NTW; nt++) {
            int nc0 = nbase + nt * 8 + tig * 2;
            float bv0 = bias[nc0], bv1 = bias[nc0 + 1];
            float v0 = acc[mt][nt][0] + bv0;
            float v1 = acc[mt][nt][1] + bv1;
            float v2 = acc[mt][nt][2] + bv0;
            float v3 = acc[mt][nt][3] + bv1;
            if (RELU) {
                v0 = fmaxf(v0, 0.f); v1 = fmaxf(v1, 0.f);
                v2 = fmaxf(v2, 0.f); v3 = fmaxf(v3, 0.f);
            }
            if (r0 < n) *(float2*)&C[(size_t)r0 * NC + nc0] = make_float2(v0, v1);
            if (r1 < n) *(float2*)&C[(size_t)r1 * NC + nc0] = make_float2(v2, v3);
        }
    }
}

// ---------------- launch ----------------
extern "C" void kernel_launch(void* const* d_in, const int* in_sizes, int n_in,
                              void* d_out, int out_size) {
    const float* feat = (const float*)d_in[0];
    const int*   src  = (const int*)  d_in[1];
    const int*   dst  = (const int*)  d_in[2];
    const float* w1   = (const float*)d_in[3];
    const float* b1   = (const float*)d_in[4];
    const float* cw1  = (const float*)d_in[5];
    const float* cb1  = (const float*)d_in[6];
    const float* cw2  = (const float*)d_in[7];
    const float* cb2  = (const float*)d_in[8];
    const float* w2   = (const float*)d_in[9];
    const float* b2   = (const float*)d_in[10];
    float* out = (float*)d_out;

    int n = in_sizes[0] / DH;   // 100000
    int E = in_sizes[1];        // 1600000

    void *p_h0, *p_f, *p_x1;
    void *p_w1hi, *p_w1lo, *p_wp1hi, *p_wp1lo, *p_wfhi, *p_wflo, *p_bf;
    cudaGetSymbolAddress(&p_h0,    g_h0);
    cudaGetSymbolAddress(&p_f,     g_f);
    cudaGetSymbolAddress(&p_x1,    g_x1);
    cudaGetSymbolAddress(&p_w1hi,  g_w1hi);
    cudaGetSymbolAddress(&p_w1lo,  g_w1lo);
    cudaGetSymbolAddress(&p_wp1hi, g_wp1hi);
    cudaGetSymbolAddress(&p_wp1lo, g_wp1lo);
    cudaGetSymbolAddress(&p_wfhi,  g_wfhi);
    cudaGetSymbolAddress(&p_wflo,  g_wflo);
    cudaGetSymbolAddress(&p_bf,    g_bf);

    // opt-in dynamic smem (128-row tiles)
    constexpr int SMEM128 = (128 * (DH + 4) + 2 * DH * (128 + 8)) * 4;  // 206848 B
    constexpr int SMEM64  = (128 * (DH + 4) + 2 * DH * (64 + 8)) * 4;   // 141312 B
    cudaFuncSetAttribute(gemm_tc_kernel<128, true>,
                         cudaFuncAttributeMaxDynamicSharedMemorySize, SMEM128);
    cudaFuncSetAttribute(gemm_tc_kernel<64, false>,
                         cudaFuncAttributeMaxDynamicSharedMemorySize, SMEM64);

    int nb   = (n + 255) / 256;
    int eb   = (E + 255) / 256;
    int gb   = (n + 127) / 128;         // gemm blocks (128-row tiles)
    int sb   = (n * 32 + 255) / 256;    // spmm blocks (warp per row)
    int nblk = (n + 255) / 256;         // scan blocks

    // 1-3: prep + degree accumulation
    prep_weights_kernel<<<DH, DH>>>(w1, cw1, cw2, w2, cb2, b2);
    zero_deg_kernel<<<nb, 256>>>(n);
    deg_kernel<<<eb, 256>>>(src, dst, E);

    // 4: fc1 (depends only on prep) — placed here so ncu capture lands on it
    gemm_tc_kernel<128, true><<<gb, 256, SMEM128>>>(feat, (const float*)p_w1hi,
        (const float*)p_w1lo, b1, (float*)p_h0, n);

    // 5-8: graph CSR build
    rs_blocksum_kernel<<<nblk, 256>>>(n);
    scan_sums_kernel<<<1, 512>>>(nblk, n);
    writeptr_kernel<<<nblk, 256>>>(n);
    fill_kernel<<<eb, 256>>>(src, dst, E);

    // 9: conv1 SpMM + residual -> f1
    spmm_kernel<<<sb, 256>>>((const float*)p_h0, (const float*)p_h0, (float*)p_f, n);

    // 10: conv1 linear: x1 = relu(f1 @ W1' + cb1)
    gemm_tc_kernel<128, true><<<gb, 256, SMEM128>>>((const float*)p_f, (const float*)p_wp1hi,
        (const float*)p_wp1lo, cb1, (float*)p_x1, n);

    // 11: conv2 SpMM + residual -> f2
    spmm_kernel<<<sb, 256>>>((const float*)p_x1, (const float*)p_h0, (float*)p_f, n);

    // 12: conv2 linear fused with fc2: out = f2 @ Wf + bf
    gemm_tc_kernel<64, false><<<gb, 256, SMEM64>>>((const float*)p_f, (const float*)p_wfhi,
        (const float*)p_wflo, (const float*)p_bf, out, n);
}

// round 5
// speedup vs baseline: 1.4945x; 1.0773x over previous
#include <cuda_runtime.h>
#include <cuda_bf16.h>
#include <math.h>
#include <stdint.h>

#define NMAX 100000
#define EMAX 1600000
#define DH   128
#define DOUT 64
#define NBLK_MAX ((NMAX + 255) / 256)   /* 391 */

// GCN2Conv constants
#define ALPHA_C  0.2f
#define BETA1_C  0.6931471805599453f   /* ln(2)   */
#define BETA2_C  0.4054651081081644f   /* ln(1.5) */

// ---------------- static device scratch (allocation-free rule) ----------------
__device__ float g_h0[NMAX * DH];
__device__ float g_f [NMAX * DH];   // reused: f1 then f2
__device__ float g_x1[NMAX * DH];
__device__ int   g_deg_out[NMAX];
__device__ int   g_deg_in [NMAX];
__device__ float g_rs_out[NMAX];
__device__ float g_rs_in [NMAX];
__device__ int   g_row_ptr[NMAX + 1];
__device__ int   g_cursor [NMAX];
__device__ int   g_cols   [EMAX];
__device__ int   g_blk_sums[NBLK_MAX + 1];
__device__ float g_wp1[DH * DH];    // (1-b1)I + b1*cw1   (fp32)
__device__ float g_wf [DH * DOUT];  // (b2*cw2+(1-b2)I) @ w2
__device__ float g_bf [DOUT];       // cb2 @ w2 + b2

// ---------------- tf32 helpers ----------------
__device__ __forceinline__ uint32_t cvt_tf32(float v) {
    uint32_t r;
    asm("cvt.rna.tf32.f32 %0, %1;" : "=r"(r) : "f"(v));
    return r;
}
__device__ __forceinline__ void mma8(float* c, const uint32_t* a, uint32_t b0, uint32_t b1) {
    asm("mma.sync.aligned.m16n8k8.row.col.f32.tf32.tf32.f32 "
        "{%0,%1,%2,%3}, {%4,%5,%6,%7}, {%8,%9}, {%0,%1,%2,%3};"
        : "+f"(c[0]), "+f"(c[1]), "+f"(c[2]), "+f"(c[3])
        : "r"(a[0]), "r"(a[1]), "r"(a[2]), "r"(a[3]), "r"(b0), "r"(b1));
}

// ---------------- setup kernels ----------------
// merged weight prep: fold W1', compute Wf + bf   <<<128,128>>>
__global__ void prep_weights_kernel(const float* __restrict__ cw1,
                                    const float* __restrict__ cw2,
                                    const float* __restrict__ w2,
                                    const float* __restrict__ cb2,
                                    const float* __restrict__ b2) {
    int k = blockIdx.x, j = threadIdx.x;
    float v = BETA1_C * cw1[k * DH + j];
    if (k == j) v += (1.0f - BETA1_C);
    g_wp1[k * DH + j] = v;
    if (j < DOUT) {
        float s = 0.0f;
        for (int m = 0; m < DH; m++) s += cw2[k * DH + m] * w2[m * DOUT + j];
        g_wf[k * DOUT + j] = BETA2_C * s + (1.0f - BETA2_C) * w2[k * DOUT + j];
        if (k == 0) {
            float t = 0.0f;
            for (int m = 0; m < DH; m++) t += cb2[m] * w2[m * DOUT + j];
            g_bf[j] = t + b2[j];
        }
    }
}

__global__ void zero_deg_kernel(int n) {
    int i = blockIdx.x * blockDim.x + threadIdx.x;
    if (i < n) { g_deg_out[i] = 0; g_deg_in[i] = 0; }
}

__global__ void deg_kernel(const int* __restrict__ src, const int* __restrict__ dst, int E) {
    int e = blockIdx.x * blockDim.x + threadIdx.x;
    if (e < E) {
        atomicAdd(&g_deg_out[src[e]], 1);
        atomicAdd(&g_deg_in [dst[e]], 1);
    }
}

// merged: rsqrt norms + per-block sums of deg_in
__global__ void rs_blocksum_kernel(int n) {
    __shared__ int warp_s[8];
    int i = blockIdx.x * 256 + threadIdx.x;
    int d_in = 0;
    if (i < n) {
        int d_out = g_deg_out[i];
        d_in = g_deg_in[i];
        g_rs_out[i] = rsqrtf(fmaxf((float)d_out, 1.0f));
        g_rs_in [i] = rsqrtf(fmaxf((float)d_in,  1.0f));
    }
    int v = d_in;
#pragma unroll
    for (int o = 16; o > 0; o >>= 1) v += __shfl_down_sync(0xffffffffu, v, o);
    if ((threadIdx.x & 31) == 0) warp_s[threadIdx.x >> 5] = v;
    __syncthreads();
    if (threadIdx.x < 8) {
        int s = warp_s[threadIdx.x];
#pragma unroll
        for (int o = 4; o > 0; o >>= 1) s += __shfl_down_sync(0xffu, s, o);
        if (threadIdx.x == 0) g_blk_sums[blockIdx.x] = s;
    }
}

__global__ void scan_sums_kernel(int nblk, int n) {
    __shared__ int sh[512];
    int t = threadIdx.x;
    sh[t] = (t < nblk) ? g_blk_sums[t] : 0;
    __syncthreads();
#pragma unroll
    for (int o = 1; o < 512; o <<= 1) {
        int v = (t >= o) ? sh[t - o] : 0;
        __syncthreads();
        sh[t] += v;
        __syncthreads();
    }
    if (t < nblk) g_blk_sums[t] = (t == 0) ? 0 : sh[t - 1];
    if (t == 0) {
        g_blk_sums[nblk] = sh[511];
        g_row_ptr[n]     = sh[511];
    }
}

__global__ void writeptr_kernel(int n) {
    __shared__ int sh[256];
    int t = threadIdx.x;
    int i = blockIdx.x * 256 + t;
    int v = (i < n) ? g_deg_in[i] : 0;
    sh[t] = v;
    __syncthreads();
#pragma unroll
    for (int o = 1; o < 256; o <<= 1) {
        int u = (t >= o) ? sh[t - o] : 0;
        __syncthreads();
        sh[t] += u;
        __syncthreads();
    }
    if (i < n) {
        int off = g_blk_sums[blockIdx.x] + sh[t] - v;  // exclusive
        g_row_ptr[i] = off;
        g_cursor [i] = off;
    }
}

__global__ void fill_kernel(const int* __restrict__ src, const int* __restrict__ dst, int E) {
    int e = blockIdx.x * blockDim.x + threadIdx.x;
    if (e < E) {
        int p = atomicAdd(&g_cursor[dst[e]], 1);
        g_cols[p] = src[e];
    }
}

// ---------------- SpMM + residual fusion ----------------
__global__ void __launch_bounds__(256) spmm_kernel(const float* __restrict__ x,
                                                   const float* __restrict__ x0,
                                                   float* __restrict__ f, int n) {
    int w    = (blockIdx.x * blockDim.x + threadIdx.x) >> 5;
    int lane = threadIdx.x & 31;
    if (w >= n) return;
    int start = g_row_ptr[w];
    int end   = g_row_ptr[w + 1];
    float4 acc = make_float4(0.f, 0.f, 0.f, 0.f);
    for (int j = start; j < end; j += 32) {
        int cnt = end - j; if (cnt > 32) cnt = 32;
        int   c  = 0;
        float sw = 0.0f;
        if (lane < cnt) { c = g_cols[j + lane]; sw = g_rs_out[c]; }
        for (int t = 0; t < cnt; t++) {
            int   cc = __shfl_sync(0xffffffffu, c,  t);
            float ww = __shfl_sync(0xffffffffu, sw, t);
            float4 v = *(const float4*)(x + (size_t)cc * DH + lane * 4);
            acc.x = fmaf(v.x, ww, acc.x);
            acc.y = fmaf(v.y, ww, acc.y);
            acc.z = fmaf(v.z, ww, acc.z);
            acc.w = fmaf(v.w, ww, acc.w);
        }
    }
    float ri = g_rs_in[w] * (1.0f - ALPHA_C);
    float4 xv = *(const float4*)(x0 + (size_t)w * DH + lane * 4);
    float4 o;
    o.x = fmaf(acc.x, ri, ALPHA_C * xv.x);
    o.y = fmaf(acc.y, ri, ALPHA_C * xv.y);
    o.z = fmaf(acc.z, ri, ALPHA_C * xv.z);
    o.w = fmaf(acc.w, ri, ALPHA_C * xv.w);
    *(float4*)(f + (size_t)w * DH + lane * 4) = o;
}

// ---------------- persistent tensor-core GEMM (3xTF32) ----------------
// C[n,NW] = A[n,128] @ B[128,NW] + bias,  NW in {128, 64}
// Block computes a 64-row x 64-col output tile. For NW=128, even/odd blocks
// own the two column halves; blocks loop over M tiles (persistent).
// B (fp32) is staged + tf32-split ONCE per block; A restaged per M tile.
// 256 threads = 8 warps in 4m x 2n; warp = 1 m16-group x 4 n8-tiles.
template <int NW, bool RELU>
__global__ void __launch_bounds__(256) gemm_tc_kernel(const float* __restrict__ A,
                                                      const float* __restrict__ B,
                                                      const float* __restrict__ bias,
                                                      float* __restrict__ C, int n) {
    constexpr int AST = DH + 4;   // 132
    constexpr int BST = 64 + 8;   // 72
    extern __shared__ float sm[];
    float* As = sm;                   // 64 x 132
    float* Bh = sm + 64 * AST;        // 128 x 72
    float* Bl = Bh + DH * BST;        // 128 x 72

    int tid = threadIdx.x;
    int nhalf, mblk, mstep;
    if (NW == 128) { nhalf = blockIdx.x & 1; mblk = blockIdx.x >> 1; mstep = gridDim.x >> 1; }
    else           { nhalf = 0;              mblk = blockIdx.x;      mstep = gridDim.x;      }

    // ---- stage + split B tile (128 x 64) once ----
    {
        const float* Bc = B + nhalf * 64;
#pragma unroll
        for (int i = 0; i < 8; i++) {
            int idx = tid + i * 256;      // 0..2047 float4s
            int row = idx >> 4;
            int c4  = idx & 15;
            float4 v = *(const float4*)(Bc + (size_t)row * NW + c4 * 4);
            float4 h, l;
            h.x = __uint_as_float(cvt_tf32(v.x)); l.x = __uint_as_float(cvt_tf32(v.x - h.x));
            h.y = __uint_as_float(cvt_tf32(v.y)); l.y = __uint_as_float(cvt_tf32(v.y - h.y));
            h.z = __uint_as_float(cvt_tf32(v.z)); l.z = __uint_as_float(cvt_tf32(v.z - h.z));
            h.w = __uint_as_float(cvt_tf32(v.w)); l.w = __uint_as_float(cvt_tf32(v.w - h.w));
            *(float4*)&Bh[row * BST + c4 * 4] = h;
            *(float4*)&Bl[row * BST + c4 * 4] = l;
        }
    }

    int warp = tid >> 5, lane = tid & 31;
    int gid  = lane >> 2, tig = lane & 3;
    int wm   = warp & 3;                 // 4 m-groups of 16 rows
    int wn   = warp >> 2;                // 2 n-groups of 32 cols
    int arow = wm * 16 + gid;

    const float4* A4 = (const float4*)A;

    for (int mb = mblk; mb * 64 < n; mb += mstep) {
        int m0 = mb * 64;
        __syncthreads();   // previous compute done (and B stage on first iter)
        // ---- stage A tile (64 x 128) ----
        size_t base4 = (size_t)m0 * (DH / 4);
#pragma unroll
        for (int i = 0; i < 8; i++) {
            int idx = tid + i * 256;      // 0..2047 float4s
            int row = idx >> 5;
            int c4  = idx & 31;
            float4 v = (m0 + row < n) ? A4[base4 + idx] : make_float4(0.f, 0.f, 0.f, 0.f);
            *(float4*)&As[row * AST + c4 * 4] = v;
        }
        __syncthreads();

        float acc[4][4];
#pragma unroll
        for (int nt = 0; nt < 4; nt++)
#pragma unroll
            for (int q = 0; q < 4; q++) acc[nt][q] = 0.f;

#pragma unroll 4
        for (int k0 = 0; k0 < DH; k0 += 8) {
            float f0 = As[arow * AST + k0 + tig];
            float f1 = As[(arow + 8) * AST + k0 + tig];
            float f2 = As[arow * AST + k0 + 4 + tig];
            float f3 = As[(arow + 8) * AST + k0 + 4 + tig];
            uint32_t ah[4], al[4];
            ah[0] = cvt_tf32(f0); al[0] = cvt_tf32(f0 - __uint_as_float(ah[0]));
            ah[1] = cvt_tf32(f1); al[1] = cvt_tf32(f1 - __uint_as_float(ah[1]));
            ah[2] = cvt_tf32(f2); al[2] = cvt_tf32(f2 - __uint_as_float(ah[2]));
            ah[3] = cvt_tf32(f3); al[3] = cvt_tf32(f3 - __uint_as_float(ah[3]));
#pragma unroll
            for (int nt = 0; nt < 4; nt++) {
                int ncol = wn * 32 + nt * 8 + gid;
                uint32_t bh0 = __float_as_uint(Bh[(k0 + tig) * BST + ncol]);
                uint32_t bh1 = __float_as_uint(Bh[(k0 + 4 + tig) * BST + ncol]);
                uint32_t bl0 = __float_as_uint(Bl[(k0 + tig) * BST + ncol]);
                uint32_t bl1 = __float_as_uint(Bl[(k0 + 4 + tig) * BST + ncol]);
                mma8(acc[nt], ah, bh0, bh1);
                mma8(acc[nt], ah, bl0, bl1);
                mma8(acc[nt], al, bh0, bh1);
            }
        }

        // ---- epilogue ----
        int r0 = m0 + wm * 16 + gid;
        int r1 = r0 + 8;
#pragma unroll
        for (int nt = 0; nt < 4; nt++) {
            int nc0 = nhalf * 64 + wn * 32 + nt * 8 + tig * 2;
            float bv0 = bias[nc0], bv1 = bias[nc0 + 1];
            float v0 = acc[nt][0] + bv0;
            float v1 = acc[nt][1] + bv1;
            float v2 = acc[nt][2] + bv0;
            float v3 = acc[nt][3] + bv1;
            if (RELU) {
                v0 = fmaxf(v0, 0.f); v1 = fmaxf(v1, 0.f);
                v2 = fmaxf(v2, 0.f); v3 = fmaxf(v3, 0.f);
            }
            if (r0 < n) *(float2*)&C[(size_t)r0 * NW + nc0] = make_float2(v0, v1);
            if (r1 < n) *(float2*)&C[(size_t)r1 * NW + nc0] = make_float2(v2, v3);
        }
    }
}

// ---------------- launch ----------------
extern "C" void kernel_launch(void* const* d_in, const int* in_sizes, int n_in,
                              void* d_out, int out_size) {
    const float* feat = (const float*)d_in[0];
    const int*   src  = (const int*)  d_in[1];
    const int*   dst  = (const int*)  d_in[2];
    const float* w1   = (const float*)d_in[3];
    const float* b1   = (const float*)d_in[4];
    const float* cw1  = (const float*)d_in[5];
    const float* cb1  = (const float*)d_in[6];
    const float* cw2  = (const float*)d_in[7];
    const float* cb2  = (const float*)d_in[8];
    const float* w2   = (const float*)d_in[9];
    const float* b2   = (const float*)d_in[10];
    float* out = (float*)d_out;

    int n = in_sizes[0] / DH;   // 100000
    int E = in_sizes[1];        // 1600000

    void *p_h0, *p_f, *p_x1, *p_wp1, *p_wf, *p_bf;
    cudaGetSymbolAddress(&p_h0,  g_h0);
    cudaGetSymbolAddress(&p_f,   g_f);
    cudaGetSymbolAddress(&p_x1,  g_x1);
    cudaGetSymbolAddress(&p_wp1, g_wp1);
    cudaGetSymbolAddress(&p_wf,  g_wf);
    cudaGetSymbolAddress(&p_bf,  g_bf);

    // smem: 64*132 + 2*128*72 floats = 107520 B -> 2 blocks/SM
    constexpr int SMEMB = (64 * (DH + 4) + 2 * DH * 72) * 4;
    cudaFuncSetAttribute(gemm_tc_kernel<128, true>,
                         cudaFuncAttributeMaxDynamicSharedMemorySize, SMEMB);
    cudaFuncSetAttribute(gemm_tc_kernel<64, false>,
                         cudaFuncAttributeMaxDynamicSharedMemorySize, SMEMB);

    int nb   = (n + 255) / 256;
    int eb   = (E + 255) / 256;
    int sb   = (n * 32 + 255) / 256;    // spmm blocks (warp per row)
    int nblk = (n + 255) / 256;         // scan blocks
    const int PG = 296;                 // persistent gemm grid = 2 blocks x 148 SMs

    // 1-3: prep + degree accumulation
    prep_weights_kernel<<<DH, DH>>>(cw1, cw2, w2, cb2, b2);
    zero_deg_kernel<<<nb, 256>>>(n);
    deg_kernel<<<eb, 256>>>(src, dst, E);

    // 4: fc1 (depends only on inputs) — ncu capture lands here
    gemm_tc_kernel<128, true><<<PG, 256, SMEMB>>>(feat, w1, b1, (float*)p_h0, n);

    // 5-8: graph CSR build
    rs_blocksum_kernel<<<nblk, 256>>>(n);
    scan_sums_kernel<<<1, 512>>>(nblk, n);
    writeptr_kernel<<<nblk, 256>>>(n);
    fill_kernel<<<eb, 256>>>(src, dst, E);

    // 9: conv1 SpMM + residual -> f1
    spmm_kernel<<<sb, 256>>>((const float*)p_h0, (const float*)p_h0, (float*)p_f, n);

    // 10: conv1 linear: x1 = relu(f1 @ W1' + cb1)
    gemm_tc_kernel<128, true><<<PG, 256, SMEMB>>>((const float*)p_f, (const float*)p_wp1,
                                                  cb1, (float*)p_x1, n);

    // 11: conv2 SpMM + residual -> f2
    spmm_kernel<<<sb, 256>>>((const float*)p_x1, (const float*)p_h0, (float*)p_f, n);

    // 12: conv2 linear fused with fc2: out = f2 @ Wf + bf
    gemm_tc_kernel<64, false><<<PG, 256, SMEMB>>>((const float*)p_f, (const float*)p_wf,
                                                  (const float*)p_bf, out, n);
}

// round 6
// speedup vs baseline: 1.7759x; 1.1883x over previous
#include <cuda_runtime.h>
#include <cuda_bf16.h>
#include <math.h>
#include <stdint.h>

#define NMAX 100000
#define EMAX 1600000
#define DH   128
#define DOUT 64
#define NBLK_MAX ((NMAX + 255) / 256)   /* 391 */

// GCN2Conv constants
#define ALPHA_C  0.2f
#define BETA1_C  0.6931471805599453f   /* ln(2)   */
#define BETA2_C  0.4054651081081644f   /* ln(1.5) */

// ---------------- static device scratch (allocation-free rule) ----------------
__device__ float g_h0[NMAX * DH];
__device__ float g_f [NMAX * DH];   // reused: f1 then f2
__device__ float g_x1[NMAX * DH];
__device__ int   g_deg_out[NMAX];
__device__ int   g_deg_in [NMAX];
__device__ float g_rs_out[NMAX];
__device__ float g_rs_in [NMAX];
__device__ int   g_row_ptr[NMAX + 1];
__device__ int   g_cursor [NMAX];
__device__ int   g_cols   [EMAX];
__device__ int   g_blk_sums[NBLK_MAX + 1];
__device__ float g_wp1[DH * DH];    // (1-b1)I + b1*cw1   (fp32)
__device__ float g_wf [DH * DOUT];  // (b2*cw2+(1-b2)I) @ w2
__device__ float g_bf [DOUT];       // cb2 @ w2 + b2

// ---------------- bf16 split helpers ----------------
__device__ __forceinline__ void bf16_split(float v, __nv_bfloat16& hi, __nv_bfloat16& lo) {
    hi = __float2bfloat16_rn(v);
    lo = __float2bfloat16_rn(v - __bfloat162float(hi));
}
__device__ __forceinline__ uint32_t pack_bf2(__nv_bfloat16 a, __nv_bfloat16 b) {
    __nv_bfloat162 p;
    p.x = a; p.y = b;
    return *(uint32_t*)&p;
}
__device__ __forceinline__ void mma16(float* c, const uint32_t* a, uint32_t b0, uint32_t b1) {
    asm("mma.sync.aligned.m16n8k16.row.col.f32.bf16.bf16.f32 "
        "{%0,%1,%2,%3}, {%4,%5,%6,%7}, {%8,%9}, {%0,%1,%2,%3};"
        : "+f"(c[0]), "+f"(c[1]), "+f"(c[2]), "+f"(c[3])
        : "r"(a[0]), "r"(a[1]), "r"(a[2]), "r"(a[3]), "r"(b0), "r"(b1));
}

// ---------------- setup kernels ----------------
// merged weight prep: fold W1', compute Wf + bf   <<<128,128>>>
__global__ void prep_weights_kernel(const float* __restrict__ cw1,
                                    const float* __restrict__ cw2,
                                    const float* __restrict__ w2,
                                    const float* __restrict__ cb2,
                                    const float* __restrict__ b2) {
    int k = blockIdx.x, j = threadIdx.x;
    float v = BETA1_C * cw1[k * DH + j];
    if (k == j) v += (1.0f - BETA1_C);
    g_wp1[k * DH + j] = v;
    if (j < DOUT) {
        float s = 0.0f;
        for (int m = 0; m < DH; m++) s += cw2[k * DH + m] * w2[m * DOUT + j];
        g_wf[k * DOUT + j] = BETA2_C * s + (1.0f - BETA2_C) * w2[k * DOUT + j];
        if (k == 0) {
            float t = 0.0f;
            for (int m = 0; m < DH; m++) t += cb2[m] * w2[m * DOUT + j];
            g_bf[j] = t + b2[j];
        }
    }
}

__global__ void zero_deg_kernel(int n) {
    int i = blockIdx.x * blockDim.x + threadIdx.x;
    if (i < n) { g_deg_out[i] = 0; g_deg_in[i] = 0; }
}

__global__ void deg_kernel(const int* __restrict__ src, const int* __restrict__ dst, int E) {
    int e = blockIdx.x * blockDim.x + threadIdx.x;
    if (e < E) {
        atomicAdd(&g_deg_out[src[e]], 1);
        atomicAdd(&g_deg_in [dst[e]], 1);
    }
}

// merged: rsqrt norms + per-block sums of deg_in
__global__ void rs_blocksum_kernel(int n) {
    __shared__ int warp_s[8];
    int i = blockIdx.x * 256 + threadIdx.x;
    int d_in = 0;
    if (i < n) {
        int d_out = g_deg_out[i];
        d_in = g_deg_in[i];
        g_rs_out[i] = rsqrtf(fmaxf((float)d_out, 1.0f));
        g_rs_in [i] = rsqrtf(fmaxf((float)d_in,  1.0f));
    }
    int v = d_in;
#pragma unroll
    for (int o = 16; o > 0; o >>= 1) v += __shfl_down_sync(0xffffffffu, v, o);
    if ((threadIdx.x & 31) == 0) warp_s[threadIdx.x >> 5] = v;
    __syncthreads();
    if (threadIdx.x < 8) {
        int s = warp_s[threadIdx.x];
#pragma unroll
        for (int o = 4; o > 0; o >>= 1) s += __shfl_down_sync(0xffu, s, o);
        if (threadIdx.x == 0) g_blk_sums[blockIdx.x] = s;
    }
}

__global__ void scan_sums_kernel(int nblk, int n) {
    __shared__ int sh[512];
    int t = threadIdx.x;
    sh[t] = (t < nblk) ? g_blk_sums[t] : 0;
    __syncthreads();
#pragma unroll
    for (int o = 1; o < 512; o <<= 1) {
        int v = (t >= o) ? sh[t - o] : 0;
        __syncthreads();
        sh[t] += v;
        __syncthreads();
    }
    if (t < nblk) g_blk_sums[t] = (t == 0) ? 0 : sh[t - 1];
    if (t == 0) {
        g_blk_sums[nblk] = sh[511];
        g_row_ptr[n]     = sh[511];
    }
}

__global__ void writeptr_kernel(int n) {
    __shared__ int sh[256];
    int t = threadIdx.x;
    int i = blockIdx.x * 256 + t;
    int v = (i < n) ? g_deg_in[i] : 0;
    sh[t] = v;
    __syncthreads();
#pragma unroll
    for (int o = 1; o < 256; o <<= 1) {
        int u = (t >= o) ? sh[t - o] : 0;
        __syncthreads();
        sh[t] += u;
        __syncthreads();
    }
    if (i < n) {
        int off = g_blk_sums[blockIdx.x] + sh[t] - v;  // exclusive
        g_row_ptr[i] = off;
        g_cursor [i] = off;
    }
}

__global__ void fill_kernel(const int* __restrict__ src, const int* __restrict__ dst, int E) {
    int e = blockIdx.x * blockDim.x + threadIdx.x;
    if (e < E) {
        int p = atomicAdd(&g_cursor[dst[e]], 1);
        g_cols[p] = src[e];
    }
}

// ---------------- SpMM + residual fusion ----------------
__global__ void __launch_bounds__(256) spmm_kernel(const float* __restrict__ x,
                                                   const float* __restrict__ x0,
                                                   float* __restrict__ f, int n) {
    int w    = (blockIdx.x * blockDim.x + threadIdx.x) >> 5;
    int lane = threadIdx.x & 31;
    if (w >= n) return;
    int start = g_row_ptr[w];
    int end   = g_row_ptr[w + 1];
    float4 acc = make_float4(0.f, 0.f, 0.f, 0.f);
    for (int j = start; j < end; j += 32) {
        int cnt = end - j; if (cnt > 32) cnt = 32;
        int   c  = 0;
        float sw = 0.0f;
        if (lane < cnt) { c = g_cols[j + lane]; sw = g_rs_out[c]; }
        for (int t = 0; t < cnt; t++) {
            int   cc = __shfl_sync(0xffffffffu, c,  t);
            float ww = __shfl_sync(0xffffffffu, sw, t);
            float4 v = *(const float4*)(x + (size_t)cc * DH + lane * 4);
            acc.x = fmaf(v.x, ww, acc.x);
            acc.y = fmaf(v.y, ww, acc.y);
            acc.z = fmaf(v.z, ww, acc.z);
            acc.w = fmaf(v.w, ww, acc.w);
        }
    }
    float ri = g_rs_in[w] * (1.0f - ALPHA_C);
    float4 xv = *(const float4*)(x0 + (size_t)w * DH + lane * 4);
    float4 o;
    o.x = fmaf(acc.x, ri, ALPHA_C * xv.x);
    o.y = fmaf(acc.y, ri, ALPHA_C * xv.y);
    o.z = fmaf(acc.z, ri, ALPHA_C * xv.z);
    o.w = fmaf(acc.w, ri, ALPHA_C * xv.w);
    *(float4*)(f + (size_t)w * DH + lane * 4) = o;
}

// ---------------- persistent tensor-core GEMM (3xBF16 split) ----------------
// C[n,NW] = A[n,128] @ B[128,NW] + bias, NW in {128,64}
// fp32 inputs split to bf16 hi/lo at staging; inner loop = pure LDS + HMMA.16816.
// A*B ~= Ahi*Bhi + Ahi*Blo + Alo*Bhi  (lo*lo term ~2^-16 relative, dropped)
// Block computes 64x64 tile; for NW=128, even/odd blocks own column halves.
// B staged+split ONCE per persistent block; A restaged per M tile.
// 256 threads = 8 warps in 4m x 2n; warp = m16 x 4 n8-tiles.
// smem strides of 68 u32 make all fragment loads bank-conflict-free.
template <int NW, bool RELU>
__global__ void __launch_bounds__(256) gemm_tc_kernel(const float* __restrict__ A,
                                                      const float* __restrict__ B,
                                                      const float* __restrict__ bias,
                                                      float* __restrict__ C, int n) {
    constexpr int AW = 68;                 // u32 stride per A row (128 bf16 + pad)
    constexpr int BW = 68;                 // u32 stride per B col (128 bf16 + pad)
    extern __shared__ uint32_t smu[];
    uint32_t* Ahi = smu;                   // 64 rows x 68
    uint32_t* Alo = Ahi + 64 * AW;
    uint32_t* Bhi = Alo + 64 * AW;         // 64 cols x 68 (transposed: k contiguous)
    uint32_t* Blo = Bhi + 64 * BW;

    int tid = threadIdx.x;
    int nhalf, mblk, mstep;
    if (NW == 128) { nhalf = blockIdx.x & 1; mblk = blockIdx.x >> 1; mstep = gridDim.x >> 1; }
    else           { nhalf = 0;              mblk = blockIdx.x;      mstep = gridDim.x;      }

    // ---- stage + split B tile (128 k x 64 n) once, stored [col][k] ----
    {
        __nv_bfloat16* BhiH = (__nv_bfloat16*)Bhi;
        __nv_bfloat16* BloH = (__nv_bfloat16*)Blo;
        const float* Bc = B + nhalf * 64;
#pragma unroll
        for (int i = 0; i < 32; i++) {
            int idx = tid + i * 256;       // 0..8191
            int k   = idx >> 6;
            int col = idx & 63;
            float v = Bc[(size_t)k * NW + col];
            __nv_bfloat16 h, l;
            bf16_split(v, h, l);
            BhiH[col * (BW * 2) + k] = h;
            BloH[col * (BW * 2) + k] = l;
        }
    }

    int warp = tid >> 5, lane = tid & 31;
    int gid  = lane >> 2, tig = lane & 3;
    int wm   = warp & 3;                 // 4 m-groups of 16 rows
    int wn   = warp >> 2;                // 2 n-groups of 32 cols
    int arow = wm * 16 + gid;

    const float4* A4 = (const float4*)A;

    for (int mb = mblk; mb * 64 < n; mb += mstep) {
        int m0 = mb * 64;
        __syncthreads();   // prev compute done (and B stage on first iter)
        // ---- stage + split A tile (64 x 128) ----
        {
            size_t base4 = (size_t)m0 * (DH / 4);
#pragma unroll
            for (int i = 0; i < 8; i++) {
                int idx = tid + i * 256;   // 0..2047 float4s
                int row = idx >> 5;
                int c4  = idx & 31;
                float4 v = (m0 + row < n) ? A4[base4 + idx] : make_float4(0.f, 0.f, 0.f, 0.f);
                __nv_bfloat16 hx, lx, hy, ly, hz, lz, hw, lw;
                bf16_split(v.x, hx, lx); bf16_split(v.y, hy, ly);
                bf16_split(v.z, hz, lz); bf16_split(v.w, hw, lw);
                Ahi[row * AW + c4 * 2]     = pack_bf2(hx, hy);
                Ahi[row * AW + c4 * 2 + 1] = pack_bf2(hz, hw);
                Alo[row * AW + c4 * 2]     = pack_bf2(lx, ly);
                Alo[row * AW + c4 * 2 + 1] = pack_bf2(lz, lw);
            }
        }
        __syncthreads();

        float acc[4][4];
#pragma unroll
        for (int nt = 0; nt < 4; nt++)
#pragma unroll
            for (int q = 0; q < 4; q++) acc[nt][q] = 0.f;

#pragma unroll
        for (int k0 = 0; k0 < DH; k0 += 16) {
            int aw = arow * AW + (k0 >> 1);
            uint32_t ah[4], al[4];
            ah[0] = Ahi[aw + tig];
            ah[1] = Ahi[aw + 8 * AW + tig];
            ah[2] = Ahi[aw + 4 + tig];
            ah[3] = Ahi[aw + 8 * AW + 4 + tig];
            al[0] = Alo[aw + tig];
            al[1] = Alo[aw + 8 * AW + tig];
            al[2] = Alo[aw + 4 + tig];
            al[3] = Alo[aw + 8 * AW + 4 + tig];
#pragma unroll
            for (int nt = 0; nt < 4; nt++) {
                int bw = (wn * 32 + nt * 8 + gid) * BW + (k0 >> 1);
                uint32_t bh0 = Bhi[bw + tig];
                uint32_t bh1 = Bhi[bw + 4 + tig];
                uint32_t bl0 = Blo[bw + tig];
                uint32_t bl1 = Blo[bw + 4 + tig];
                mma16(acc[nt], ah, bh0, bh1);
                mma16(acc[nt], ah, bl0, bl1);
                mma16(acc[nt], al, bh0, bh1);
            }
        }

        // ---- epilogue ----
        int r0 = m0 + wm * 16 + gid;
        int r1 = r0 + 8;
#pragma unroll
        for (int nt = 0; nt < 4; nt++) {
            int nc0 = nhalf * 64 + wn * 32 + nt * 8 + tig * 2;
            float bv0 = bias[nc0], bv1 = bias[nc0 + 1];
            float v0 = acc[nt][0] + bv0;
            float v1 = acc[nt][1] + bv1;
            float v2 = acc[nt][2] + bv0;
            float v3 = acc[nt][3] + bv1;
            if (RELU) {
                v0 = fmaxf(v0, 0.f); v1 = fmaxf(v1, 0.f);
                v2 = fmaxf(v2, 0.f); v3 = fmaxf(v3, 0.f);
            }
            if (r0 < n) *(float2*)&C[(size_t)r0 * NW + nc0] = make_float2(v0, v1);
            if (r1 < n) *(float2*)&C[(size_t)r1 * NW + nc0] = make_float2(v2, v3);
        }
    }
}

// ---------------- launch ----------------
extern "C" void kernel_launch(void* const* d_in, const int* in_sizes, int n_in,
                              void* d_out, int out_size) {
    const float* feat = (const float*)d_in[0];
    const int*   src  = (const int*)  d_in[1];
    const int*   dst  = (const int*)  d_in[2];
    const float* w1   = (const float*)d_in[3];
    const float* b1   = (const float*)d_in[4];
    const float* cw1  = (const float*)d_in[5];
    const float* cb1  = (const float*)d_in[6];
    const float* cw2  = (const float*)d_in[7];
    const float* cb2  = (const float*)d_in[8];
    const float* w2   = (const float*)d_in[9];
    const float* b2   = (const float*)d_in[10];
    float* out = (float*)d_out;

    int n = in_sizes[0] / DH;   // 100000
    int E = in_sizes[1];        // 1600000

    void *p_h0, *p_f, *p_x1, *p_wp1, *p_wf, *p_bf;
    cudaGetSymbolAddress(&p_h0,  g_h0);
    cudaGetSymbolAddress(&p_f,   g_f);
    cudaGetSymbolAddress(&p_x1,  g_x1);
    cudaGetSymbolAddress(&p_wp1, g_wp1);
    cudaGetSymbolAddress(&p_wf,  g_wf);
    cudaGetSymbolAddress(&p_bf,  g_bf);

    // smem: 4 arrays x 64*68 u32 = 69632 B -> 3 blocks/SM
    constexpr int SMEMB = 4 * 64 * 68 * 4;
    cudaFuncSetAttribute(gemm_tc_kernel<128, true>,
                         cudaFuncAttributeMaxDynamicSharedMemorySize, SMEMB);
    cudaFuncSetAttribute(gemm_tc_kernel<64, false>,
                         cudaFuncAttributeMaxDynamicSharedMemorySize, SMEMB);

    int nb   = (n + 255) / 256;
    int eb   = (E + 255) / 256;
    int sb   = (n * 32 + 255) / 256;    // spmm blocks (warp per row)
    int nblk = (n + 255) / 256;         // scan blocks
    const int PG = 444;                 // persistent gemm grid = 3 blocks x 148 SMs

    // 1-3: prep + degree accumulation
    prep_weights_kernel<<<DH, DH>>>(cw1, cw2, w2, cb2, b2);
    zero_deg_kernel<<<nb, 256>>>(n);
    deg_kernel<<<eb, 256>>>(src, dst, E);

    // 4: fc1 (depends only on inputs) — ncu capture lands here
    gemm_tc_kernel<128, true><<<PG, 256, SMEMB>>>(feat, w1, b1, (float*)p_h0, n);

    // 5-8: graph CSR build
    rs_blocksum_kernel<<<nblk, 256>>>(n);
    scan_sums_kernel<<<1, 512>>>(nblk, n);
    writeptr_kernel<<<nblk, 256>>>(n);
    fill_kernel<<<eb, 256>>>(src, dst, E);

    // 9: conv1 SpMM + residual -> f1
    spmm_kernel<<<sb, 256>>>((const float*)p_h0, (const float*)p_h0, (float*)p_f, n);

    // 10: conv1 linear: x1 = relu(f1 @ W1' + cb1)
    gemm_tc_kernel<128, true><<<PG, 256, SMEMB>>>((const float*)p_f, (const float*)p_wp1,
                                                  cb1, (float*)p_x1, n);

    // 11: conv2 SpMM + residual -> f2
    spmm_kernel<<<sb, 256>>>((const float*)p_x1, (const float*)p_h0, (float*)p_f, n);

    // 12: conv2 linear fused with fc2: out = f2 @ Wf + bf
    gemm_tc_kernel<64, false><<<PG, 256, SMEMB>>>((const float*)p_f, (const float*)p_wf,
                                                  (const float*)p_bf, out, n);
}

// round 7
// speedup vs baseline: 2.0268x; 1.1412x over previous
#include <cuda_runtime.h>
#include <cuda_bf16.h>
#include <cuda_fp16.h>
#include <math.h>
#include <stdint.h>

#define NMAX 100000
#define EMAX 1600000
#define DH   128
#define DOUT 64
#define NBLK_MAX ((NMAX + 255) / 256)   /* 391 */

// GCN2Conv constants
#define ALPHA_C  0.2f
#define BETA1_C  0.6931471805599453f   /* ln(2)   */
#define BETA2_C  0.4054651081081644f   /* ln(1.5) */

// ---------------- static device scratch (allocation-free rule) ----------------
__device__ float  g_h0[NMAX * DH];      // fc1 output fp32 (residual source)
__device__ __half g_xh[NMAX * DH];      // fp16 gather source (h0 then x1)
__device__ float  g_f [NMAX * DH];      // spmm output, reused
__device__ int    g_deg_out[NMAX];
__device__ int    g_deg_in [NMAX];
__device__ float  g_rs_out[NMAX];
__device__ float  g_rs_in [NMAX];
__device__ int    g_row_ptr[NMAX + 1];
__device__ int    g_cursor [NMAX];
__device__ int    g_cols   [EMAX];
__device__ int    g_blk_sums[NBLK_MAX + 1];
__device__ float  g_wp1[DH * DH];    // (1-b1)I + b1*cw1   (fp32)
__device__ float  g_wf [DH * DOUT];  // (b2*cw2+(1-b2)I) @ w2
__device__ float  g_bf [DOUT];       // cb2 @ w2 + b2

// ---------------- bf16 split helpers ----------------
__device__ __forceinline__ void bf16_split(float v, __nv_bfloat16& hi, __nv_bfloat16& lo) {
    hi = __float2bfloat16_rn(v);
    lo = __float2bfloat16_rn(v - __bfloat162float(hi));
}
__device__ __forceinline__ uint32_t pack_bf2(__nv_bfloat16 a, __nv_bfloat16 b) {
    __nv_bfloat162 p;
    p.x = a; p.y = b;
    return *(uint32_t*)&p;
}
__device__ __forceinline__ void mma16(float* c, const uint32_t* a, uint32_t b0, uint32_t b1) {
    asm("mma.sync.aligned.m16n8k16.row.col.f32.bf16.bf16.f32 "
        "{%0,%1,%2,%3}, {%4,%5,%6,%7}, {%8,%9}, {%0,%1,%2,%3};"
        : "+f"(c[0]), "+f"(c[1]), "+f"(c[2]), "+f"(c[3])
        : "r"(a[0]), "r"(a[1]), "r"(a[2]), "r"(a[3]), "r"(b0), "r"(b1));
}
__device__ __forceinline__ void ldsm_x4(uint32_t addr, uint32_t* r) {
    asm volatile("ldmatrix.sync.aligned.m8n8.x4.shared.b16 {%0,%1,%2,%3}, [%4];"
                 : "=r"(r[0]), "=r"(r[1]), "=r"(r[2]), "=r"(r[3]) : "r"(addr));
}
__device__ __forceinline__ void ldsm_x2(uint32_t addr, uint32_t& r0, uint32_t& r1) {
    asm volatile("ldmatrix.sync.aligned.m8n8.x2.shared.b16 {%0,%1}, [%2];"
                 : "=r"(r0), "=r"(r1) : "r"(addr));
}

// ---------------- setup kernels ----------------
__global__ void prep_weights_kernel(const float* __restrict__ cw1,
                                    const float* __restrict__ cw2,
                                    const float* __restrict__ w2,
                                    const float* __restrict__ cb2,
                                    const float* __restrict__ b2) {
    int k = blockIdx.x, j = threadIdx.x;
    float v = BETA1_C * cw1[k * DH + j];
    if (k == j) v += (1.0f - BETA1_C);
    g_wp1[k * DH + j] = v;
    if (j < DOUT) {
        float s = 0.0f;
        for (int m = 0; m < DH; m++) s += cw2[k * DH + m] * w2[m * DOUT + j];
        g_wf[k * DOUT + j] = BETA2_C * s + (1.0f - BETA2_C) * w2[k * DOUT + j];
        if (k == 0) {
            float t = 0.0f;
            for (int m = 0; m < DH; m++) t += cb2[m] * w2[m * DOUT + j];
            g_bf[j] = t + b2[j];
        }
    }
}

__global__ void zero_deg_kernel(int n) {
    int i = blockIdx.x * blockDim.x + threadIdx.x;
    if (i < n) { g_deg_out[i] = 0; g_deg_in[i] = 0; }
}

__global__ void deg_kernel(const int* __restrict__ src, const int* __restrict__ dst, int E) {
    int e = blockIdx.x * blockDim.x + threadIdx.x;
    if (e < E) {
        atomicAdd(&g_deg_out[src[e]], 1);
        atomicAdd(&g_deg_in [dst[e]], 1);
    }
}

__global__ void rs_blocksum_kernel(int n) {
    __shared__ int warp_s[8];
    int i = blockIdx.x * 256 + threadIdx.x;
    int d_in = 0;
    if (i < n) {
        int d_out = g_deg_out[i];
        d_in = g_deg_in[i];
        g_rs_out[i] = rsqrtf(fmaxf((float)d_out, 1.0f));
        g_rs_in [i] = rsqrtf(fmaxf((float)d_in,  1.0f));
    }
    int v = d_in;
#pragma unroll
    for (int o = 16; o > 0; o >>= 1) v += __shfl_down_sync(0xffffffffu, v, o);
    if ((threadIdx.x & 31) == 0) warp_s[threadIdx.x >> 5] = v;
    __syncthreads();
    if (threadIdx.x < 8) {
        int s = warp_s[threadIdx.x];
#pragma unroll
        for (int o = 4; o > 0; o >>= 1) s += __shfl_down_sync(0xffu, s, o);
        if (threadIdx.x == 0) g_blk_sums[blockIdx.x] = s;
    }
}

__global__ void scan_sums_kernel(int nblk, int n) {
    __shared__ int sh[512];
    int t = threadIdx.x;
    sh[t] = (t < nblk) ? g_blk_sums[t] : 0;
    __syncthreads();
#pragma unroll
    for (int o = 1; o < 512; o <<= 1) {
        int v = (t >= o) ? sh[t - o] : 0;
        __syncthreads();
        sh[t] += v;
        __syncthreads();
    }
    if (t < nblk) g_blk_sums[t] = (t == 0) ? 0 : sh[t - 1];
    if (t == 0) {
        g_blk_sums[nblk] = sh[511];
        g_row_ptr[n]     = sh[511];
    }
}

__global__ void writeptr_kernel(int n) {
    __shared__ int sh[256];
    int t = threadIdx.x;
    int i = blockIdx.x * 256 + t;
    int v = (i < n) ? g_deg_in[i] : 0;
    sh[t] = v;
    __syncthreads();
#pragma unroll
    for (int o = 1; o < 256; o <<= 1) {
        int u = (t >= o) ? sh[t - o] : 0;
        __syncthreads();
        sh[t] += u;
        __syncthreads();
    }
    if (i < n) {
        int off = g_blk_sums[blockIdx.x] + sh[t] - v;  // exclusive
        g_row_ptr[i] = off;
        g_cursor [i] = off;
    }
}

__global__ void fill_kernel(const int* __restrict__ src, const int* __restrict__ dst, int E) {
    int e = blockIdx.x * blockDim.x + threadIdx.x;
    if (e < E) {
        int p = atomicAdd(&g_cursor[dst[e]], 1);
        g_cols[p] = src[e];
    }
}

// ---------------- SpMM + residual fusion (fp16 gather, fp32 accumulate) ----------------
// f[i] = 0.8 * rs_in[i] * sum_{s in N(i)} xh[s]*rs_out[s]  +  0.2 * x0[i]
// warp per dst row; lane owns 4 columns (8 bytes fp16 per neighbor)
__global__ void __launch_bounds__(256) spmm_kernel(const __half* __restrict__ xh,
                                                   const float* __restrict__ x0,
                                                   float* __restrict__ f, int n) {
    int w    = (blockIdx.x * blockDim.x + threadIdx.x) >> 5;
    int lane = threadIdx.x & 31;
    if (w >= n) return;
    int start = g_row_ptr[w];
    int end   = g_row_ptr[w + 1];
    float4 acc = make_float4(0.f, 0.f, 0.f, 0.f);
    for (int j = start; j < end; j += 32) {
        int cnt = end - j; if (cnt > 32) cnt = 32;
        int   c  = 0;
        float sw = 0.0f;
        if (lane < cnt) { c = g_cols[j + lane]; sw = g_rs_out[c]; }
        for (int t = 0; t < cnt; t++) {
            int   cc = __shfl_sync(0xffffffffu, c,  t);
            float ww = __shfl_sync(0xffffffffu, sw, t);
            uint2 raw = *(const uint2*)(xh + (size_t)cc * DH + lane * 4);
            float2 v01 = __half22float2(*(const __half2*)&raw.x);
            float2 v23 = __half22float2(*(const __half2*)&raw.y);
            acc.x = fmaf(v01.x, ww, acc.x);
            acc.y = fmaf(v01.y, ww, acc.y);
            acc.z = fmaf(v23.x, ww, acc.z);
            acc.w = fmaf(v23.y, ww, acc.w);
        }
    }
    float ri = g_rs_in[w] * (1.0f - ALPHA_C);
    float4 xv = *(const float4*)(x0 + (size_t)w * DH + lane * 4);
    float4 o;
    o.x = fmaf(acc.x, ri, ALPHA_C * xv.x);
    o.y = fmaf(acc.y, ri, ALPHA_C * xv.y);
    o.z = fmaf(acc.z, ri, ALPHA_C * xv.z);
    o.w = fmaf(acc.w, ri, ALPHA_C * xv.w);
    *(float4*)(f + (size_t)w * DH + lane * 4) = o;
}

// ---------------- persistent tensor-core GEMM (3xBF16 split, ldmatrix) ----------------
// C[n,NW] = A[n,128] @ B[128,NW] + bias, NW in {128,64}
// WMODE: 0 = write fp32 C only; 1 = fp32 C + fp16 C16; 2 = fp16 C16 only
template <int NW, bool RELU, int WMODE>
__global__ void __launch_bounds__(256) gemm_tc_kernel(const float* __restrict__ A,
                                                      const float* __restrict__ B,
                                                      const float* __restrict__ bias,
                                                      float* __restrict__ C,
                                                      __half* __restrict__ C16, int n) {
    constexpr int AW = 68;                 // u32 stride per A row (64 kwords + pad)
    constexpr int BW = 68;                 // u32 stride per B col
    extern __shared__ uint32_t smu[];
    uint32_t* Ahi = smu;                   // 64 rows x 68
    uint32_t* Alo = Ahi + 64 * AW;
    uint32_t* Bhi = Alo + 64 * AW;         // 64 cols x 68 ([col][kword])
    uint32_t* Blo = Bhi + 64 * BW;

    int tid = threadIdx.x;
    int nhalf, mblk, mstep;
    if (NW == 128) { nhalf = blockIdx.x & 1; mblk = blockIdx.x >> 1; mstep = gridDim.x >> 1; }
    else           { nhalf = 0;              mblk = blockIdx.x;      mstep = gridDim.x;      }

    // ---- stage + split B tile (128 k x 64 n) once, stored [col][k] ----
    {
        __nv_bfloat16* BhiH = (__nv_bfloat16*)Bhi;
        __nv_bfloat16* BloH = (__nv_bfloat16*)Blo;
        const float* Bc = B + nhalf * 64;
#pragma unroll
        for (int i = 0; i < 32; i++) {
            int idx = tid + i * 256;       // 0..8191
            int k   = idx >> 6;
            int col = idx & 63;
            float v = Bc[(size_t)k * NW + col];
            __nv_bfloat16 h, l;
            bf16_split(v, h, l);
            BhiH[col * (BW * 2) + k] = h;
            BloH[col * (BW * 2) + k] = l;
        }
    }

    int warp = tid >> 5, lane = tid & 31;
    int gid  = lane >> 2, tig = lane & 3;
    int wm   = warp & 3;                 // 4 m-groups of 16 rows
    int wn   = warp >> 2;                // 2 n-groups of 32 cols

    // ldmatrix per-lane byte offsets
    // A x4: matrices [m0-7/k0-3w][m8-15/k0-3w][m0-7/k4-7w][m8-15/k4-7w]
    int a_row = wm * 16 + (lane & 7) + ((lane >> 3) & 1) * 8;
    int a_kx  = (lane >> 4) * 4;
    uint32_t a_off = (uint32_t)(a_row * AW + a_kx) * 4u;
    // B x2: matrices [n0-7/k0-3w][n0-7/k4-7w]; lanes>=16 unused
    int b_col = wn * 32 + (lane & 7);
    int b_kx  = ((lane >> 3) & 1) * 4;
    uint32_t b_off = (uint32_t)(b_col * BW + b_kx) * 4u;

    uint32_t sAhi = (uint32_t)__cvta_generic_to_shared(Ahi);
    uint32_t sAlo = (uint32_t)__cvta_generic_to_shared(Alo);
    uint32_t sBhi = (uint32_t)__cvta_generic_to_shared(Bhi);
    uint32_t sBlo = (uint32_t)__cvta_generic_to_shared(Blo);

    const float4* A4 = (const float4*)A;

    for (int mb = mblk; mb * 64 < n; mb += mstep) {
        int m0 = mb * 64;
        __syncthreads();   // prev compute done (and B stage on first iter)
        // ---- stage + split A tile (64 x 128) ----
        {
            size_t base4 = (size_t)m0 * (DH / 4);
#pragma unroll
            for (int i = 0; i < 8; i++) {
                int idx = tid + i * 256;   // 0..2047 float4s
                int row = idx >> 5;
                int c4  = idx & 31;
                float4 v = (m0 + row < n) ? A4[base4 + idx] : make_float4(0.f, 0.f, 0.f, 0.f);
                __nv_bfloat16 hx, lx, hy, ly, hz, lz, hw, lw;
                bf16_split(v.x, hx, lx); bf16_split(v.y, hy, ly);
                bf16_split(v.z, hz, lz); bf16_split(v.w, hw, lw);
                Ahi[row * AW + c4 * 2]     = pack_bf2(hx, hy);
                Ahi[row * AW + c4 * 2 + 1] = pack_bf2(hz, hw);
                Alo[row * AW + c4 * 2]     = pack_bf2(lx, ly);
                Alo[row * AW + c4 * 2 + 1] = pack_bf2(lz, lw);
            }
        }
        __syncthreads();

        float acc[4][4];
#pragma unroll
        for (int nt = 0; nt < 4; nt++)
#pragma unroll
            for (int q = 0; q < 4; q++) acc[nt][q] = 0.f;

#pragma unroll
        for (int k0 = 0; k0 < DH; k0 += 16) {
            uint32_t kb = (uint32_t)(k0 >> 1) * 4u;
            uint32_t ah[4], al[4];
            ldsm_x4(sAhi + a_off + kb, ah);
            ldsm_x4(sAlo + a_off + kb, al);
#pragma unroll
            for (int nt = 0; nt < 4; nt++) {
                uint32_t bo = b_off + (uint32_t)(nt * 8 * BW) * 4u + kb;
                uint32_t bh0, bh1, bl0, bl1;
                ldsm_x2(sBhi + bo, bh0, bh1);
                ldsm_x2(sBlo + bo, bl0, bl1);
                mma16(acc[nt], ah, bh0, bh1);
                mma16(acc[nt], ah, bl0, bl1);
                mma16(acc[nt], al, bh0, bh1);
            }
        }

        // ---- epilogue ----
        int r0 = m0 + wm * 16 + gid;
        int r1 = r0 + 8;
#pragma unroll
        for (int nt = 0; nt < 4; nt++) {
            int nc0 = nhalf * 64 + wn * 32 + nt * 8 + tig * 2;
            float bv0 = bias[nc0], bv1 = bias[nc0 + 1];
            float v0 = acc[nt][0] + bv0;
            float v1 = acc[nt][1] + bv1;
            float v2 = acc[nt][2] + bv0;
            float v3 = acc[nt][3] + bv1;
            if (RELU) {
                v0 = fmaxf(v0, 0.f); v1 = fmaxf(v1, 0.f);
                v2 = fmaxf(v2, 0.f); v3 = fmaxf(v3, 0.f);
            }
            if (r0 < n) {
                if (WMODE != 2) *(float2*)&C[(size_t)r0 * NW + nc0] = make_float2(v0, v1);
                if (WMODE != 0) *(__half2*)&C16[(size_t)r0 * NW + nc0] = __floats2half2_rn(v0, v1);
            }
            if (r1 < n) {
                if (WMODE != 2) *(float2*)&C[(size_t)r1 * NW + nc0] = make_float2(v2, v3);
                if (WMODE != 0) *(__half2*)&C16[(size_t)r1 * NW + nc0] = __floats2half2_rn(v2, v3);
            }
        }
    }
}

// ---------------- launch ----------------
extern "C" void kernel_launch(void* const* d_in, const int* in_sizes, int n_in,
                              void* d_out, int out_size) {
    const float* feat = (const float*)d_in[0];
    const int*   src  = (const int*)  d_in[1];
    const int*   dst  = (const int*)  d_in[2];
    const float* w1   = (const float*)d_in[3];
    const float* b1   = (const float*)d_in[4];
    const float* cw1  = (const float*)d_in[5];
    const float* cb1  = (const float*)d_in[6];
    const float* cw2  = (const float*)d_in[7];
    const float* cb2  = (const float*)d_in[8];
    const float* w2   = (const float*)d_in[9];
    const float* b2   = (const float*)d_in[10];
    float* out = (float*)d_out;

    int n = in_sizes[0] / DH;   // 100000
    int E = in_sizes[1];        // 1600000

    void *p_h0, *p_xh, *p_f, *p_wp1, *p_wf, *p_bf;
    cudaGetSymbolAddress(&p_h0,  g_h0);
    cudaGetSymbolAddress(&p_xh,  g_xh);
    cudaGetSymbolAddress(&p_f,   g_f);
    cudaGetSymbolAddress(&p_wp1, g_wp1);
    cudaGetSymbolAddress(&p_wf,  g_wf);
    cudaGetSymbolAddress(&p_bf,  g_bf);

    // smem: 4 arrays x 64*68 u32 = 69632 B -> 3 blocks/SM
    constexpr int SMEMB = 4 * 64 * 68 * 4;
    cudaFuncSetAttribute(gemm_tc_kernel<128, true, 1>,
                         cudaFuncAttributeMaxDynamicSharedMemorySize, SMEMB);
    cudaFuncSetAttribute(gemm_tc_kernel<128, true, 2>,
                         cudaFuncAttributeMaxDynamicSharedMemorySize, SMEMB);
    cudaFuncSetAttribute(gemm_tc_kernel<64, false, 0>,
                         cudaFuncAttributeMaxDynamicSharedMemorySize, SMEMB);

    int nb   = (n + 255) / 256;
    int eb   = (E + 255) / 256;
    int sb   = (n * 32 + 255) / 256;    // spmm blocks (warp per row)
    int nblk = (n + 255) / 256;         // scan blocks
    const int PG = 444;                 // persistent gemm grid = 3 blocks x 148 SMs

    // 1-3: prep + degree accumulation
    prep_weights_kernel<<<DH, DH>>>(cw1, cw2, w2, cb2, b2);
    zero_deg_kernel<<<nb, 256>>>(n);
    deg_kernel<<<eb, 256>>>(src, dst, E);

    // 4: fc1 -> h0 (fp32) + xh (fp16)   — ncu capture lands here
    gemm_tc_kernel<128, true, 1><<<PG, 256, SMEMB>>>(feat, w1, b1,
        (float*)p_h0, (__half*)p_xh, n);

    // 5-8: graph CSR build
    rs_blocksum_kernel<<<nblk, 256>>>(n);
    scan_sums_kernel<<<1, 512>>>(nblk, n);
    writeptr_kernel<<<nblk, 256>>>(n);
    fill_kernel<<<eb, 256>>>(src, dst, E);

    // 9: conv1 SpMM + residual -> f1
    spmm_kernel<<<sb, 256>>>((const __half*)p_xh, (const float*)p_h0, (float*)p_f, n);

    // 10: conv1 linear: xh = relu(f1 @ W1' + cb1)   (fp16 only — sole consumer is spmm2)
    gemm_tc_kernel<128, true, 2><<<PG, 256, SMEMB>>>((const float*)p_f, (const float*)p_wp1,
        cb1, (float*)nullptr, (__half*)p_xh, n);

    // 11: conv2 SpMM + residual -> f2
    spmm_kernel<<<sb, 256>>>((const __half*)p_xh, (const float*)p_h0, (float*)p_f, n);

    // 12: conv2 linear fused with fc2: out = f2 @ Wf + bf
    gemm_tc_kernel<64, false, 0><<<PG, 256, SMEMB>>>((const float*)p_f, (const float*)p_wf,
        (const float*)p_bf, out, (__half*)nullptr, n);
}

// round 8
// speedup vs baseline: 2.0546x; 1.0137x over previous
#include <cuda_runtime.h>
#include <cuda_bf16.h>
#include <cuda_fp16.h>
#include <math.h>
#include <stdint.h>

#define NMAX 100000
#define EMAX 1600000
#define DH   128
#define DOUT 64
#define NBLK_MAX ((NMAX + 255) / 256)   /* 391 */

#define ALPHA_C  0.2f
#define BETA1_C  0.6931471805599453f   /* ln(2)   */
#define BETA2_C  0.4054651081081644f   /* ln(1.5) */

// ---------------- static device scratch ----------------
__device__ float  g_h0[NMAX * DH];      // fc1 output fp32 (residual source)
__device__ __half g_xh[NMAX * DH];      // fp16 gather source (h0 then x1)
__device__ float  g_f [NMAX * DH];      // spmm output, reused
__device__ int    g_deg_out[NMAX];
__device__ int    g_deg_in [NMAX];
__device__ float  g_rs_out[NMAX];
__device__ float  g_rs_in [NMAX];
__device__ int    g_row_ptr[NMAX + 1];
__device__ int    g_cursor [NMAX];
__device__ int    g_cols   [EMAX];
__device__ int    g_blk_sums[NBLK_MAX + 1];
__device__ float  g_wp1[DH * DH];
__device__ float  g_wf [DH * DOUT];
__device__ float  g_bf [DOUT];

// ---------------- bf16 / mma helpers ----------------
__device__ __forceinline__ void bf16_split(float v, __nv_bfloat16& hi, __nv_bfloat16& lo) {
    hi = __float2bfloat16_rn(v);
    lo = __float2bfloat16_rn(v - __bfloat162float(hi));
}
__device__ __forceinline__ uint32_t pack_bf2(__nv_bfloat16 a, __nv_bfloat16 b) {
    __nv_bfloat162 p;
    p.x = a; p.y = b;
    return *(uint32_t*)&p;
}
__device__ __forceinline__ void mma16(float* c, const uint32_t* a, uint32_t b0, uint32_t b1) {
    asm("mma.sync.aligned.m16n8k16.row.col.f32.bf16.bf16.f32 "
        "{%0,%1,%2,%3}, {%4,%5,%6,%7}, {%8,%9}, {%0,%1,%2,%3};"
        : "+f"(c[0]), "+f"(c[1]), "+f"(c[2]), "+f"(c[3])
        : "r"(a[0]), "r"(a[1]), "r"(a[2]), "r"(a[3]), "r"(b0), "r"(b1));
}
__device__ __forceinline__ void ldsm_x4(uint32_t addr, uint32_t* r) {
    asm volatile("ldmatrix.sync.aligned.m8n8.x4.shared.b16 {%0,%1,%2,%3}, [%4];"
                 : "=r"(r[0]), "=r"(r[1]), "=r"(r[2]), "=r"(r[3]) : "r"(addr));
}

// ---------------- setup kernels ----------------
__global__ void prep_weights_kernel(const float* __restrict__ cw1,
                                    const float* __restrict__ cw2,
                                    const float* __restrict__ w2,
                                    const float* __restrict__ cb2,
                                    const float* __restrict__ b2) {
    int k = blockIdx.x, j = threadIdx.x;
    float v = BETA1_C * cw1[k * DH + j];
    if (k == j) v += (1.0f - BETA1_C);
    g_wp1[k * DH + j] = v;
    if (j < DOUT) {
        float s = 0.0f;
        for (int m = 0; m < DH; m++) s += cw2[k * DH + m] * w2[m * DOUT + j];
        g_wf[k * DOUT + j] = BETA2_C * s + (1.0f - BETA2_C) * w2[k * DOUT + j];
        if (k == 0) {
            float t = 0.0f;
            for (int m = 0; m < DH; m++) t += cb2[m] * w2[m * DOUT + j];
            g_bf[j] = t + b2[j];
        }
    }
}

__global__ void zero_deg_kernel(int n) {
    int i = blockIdx.x * blockDim.x + threadIdx.x;
    if (i < n) { g_deg_out[i] = 0; g_deg_in[i] = 0; }
}

__global__ void deg_kernel(const int* __restrict__ src, const int* __restrict__ dst, int E) {
    int e = blockIdx.x * blockDim.x + threadIdx.x;
    if (e < E) {
        atomicAdd(&g_deg_out[src[e]], 1);
        atomicAdd(&g_deg_in [dst[e]], 1);
    }
}

__global__ void rs_blocksum_kernel(int n) {
    __shared__ int warp_s[8];
    int i = blockIdx.x * 256 + threadIdx.x;
    int d_in = 0;
    if (i < n) {
        int d_out = g_deg_out[i];
        d_in = g_deg_in[i];
        g_rs_out[i] = rsqrtf(fmaxf((float)d_out, 1.0f));
        g_rs_in [i] = rsqrtf(fmaxf((float)d_in,  1.0f));
    }
    int v = d_in;
#pragma unroll
    for (int o = 16; o > 0; o >>= 1) v += __shfl_down_sync(0xffffffffu, v, o);
    if ((threadIdx.x & 31) == 0) warp_s[threadIdx.x >> 5] = v;
    __syncthreads();
    if (threadIdx.x < 8) {
        int s = warp_s[threadIdx.x];
#pragma unroll
        for (int o = 4; o > 0; o >>= 1) s += __shfl_down_sync(0xffu, s, o);
        if (threadIdx.x == 0) g_blk_sums[blockIdx.x] = s;
    }
}

__global__ void scan_sums_kernel(int nblk, int n) {
    __shared__ int sh[512];
    int t = threadIdx.x;
    sh[t] = (t < nblk) ? g_blk_sums[t] : 0;
    __syncthreads();
#pragma unroll
    for (int o = 1; o < 512; o <<= 1) {
        int v = (t >= o) ? sh[t - o] : 0;
        __syncthreads();
        sh[t] += v;
        __syncthreads();
    }
    if (t < nblk) g_blk_sums[t] = (t == 0) ? 0 : sh[t - 1];
    if (t == 0) {
        g_blk_sums[nblk] = sh[511];
        g_row_ptr[n]     = sh[511];
    }
}

__global__ void writeptr_kernel(int n) {
    __shared__ int sh[256];
    int t = threadIdx.x;
    int i = blockIdx.x * 256 + t;
    int v = (i < n) ? g_deg_in[i] : 0;
    sh[t] = v;
    __syncthreads();
#pragma unroll
    for (int o = 1; o < 256; o <<= 1) {
        int u = (t >= o) ? sh[t - o] : 0;
        __syncthreads();
        sh[t] += u;
        __syncthreads();
    }
    if (i < n) {
        int off = g_blk_sums[blockIdx.x] + sh[t] - v;
        g_row_ptr[i] = off;
        g_cursor [i] = off;
    }
}

__global__ void fill_kernel(const int* __restrict__ src, const int* __restrict__ dst, int E) {
    int e = blockIdx.x * blockDim.x + threadIdx.x;
    if (e < E) {
        int p = atomicAdd(&g_cursor[dst[e]], 1);
        g_cols[p] = src[e];
    }
}

// ---------------- SpMM + residual (fp16 gather, fp32 accumulate, 4x MLP) ----------------
__global__ void __launch_bounds__(256) spmm_kernel(const __half* __restrict__ xh,
                                                   const float* __restrict__ x0,
                                                   float* __restrict__ f, int n) {
    int w    = (blockIdx.x * blockDim.x + threadIdx.x) >> 5;
    int lane = threadIdx.x & 31;
    if (w >= n) return;
    int start = g_row_ptr[w];
    int end   = g_row_ptr[w + 1];
    float4 acc = make_float4(0.f, 0.f, 0.f, 0.f);
    for (int j = start; j < end; j += 32) {
        int cnt = end - j; if (cnt > 32) cnt = 32;
        int   c  = 0;
        float sw = 0.0f;
        if (lane < cnt) { c = g_cols[j + lane]; sw = g_rs_out[c]; }
        int t = 0;
        for (; t + 4 <= cnt; t += 4) {
            int   c0 = __shfl_sync(0xffffffffu, c,  t);
            int   c1 = __shfl_sync(0xffffffffu, c,  t + 1);
            int   c2 = __shfl_sync(0xffffffffu, c,  t + 2);
            int   c3 = __shfl_sync(0xffffffffu, c,  t + 3);
            float w0 = __shfl_sync(0xffffffffu, sw, t);
            float w1 = __shfl_sync(0xffffffffu, sw, t + 1);
            float w2 = __shfl_sync(0xffffffffu, sw, t + 2);
            float w3 = __shfl_sync(0xffffffffu, sw, t + 3);
            uint2 r0 = *(const uint2*)(xh + (size_t)c0 * DH + lane * 4);
            uint2 r1 = *(const uint2*)(xh + (size_t)c1 * DH + lane * 4);
            uint2 r2 = *(const uint2*)(xh + (size_t)c2 * DH + lane * 4);
            uint2 r3 = *(const uint2*)(xh + (size_t)c3 * DH + lane * 4);
            float2 a0 = __half22float2(*(const __half2*)&r0.x);
            float2 b0 = __half22float2(*(const __half2*)&r0.y);
            acc.x = fmaf(a0.x, w0, acc.x); acc.y = fmaf(a0.y, w0, acc.y);
            acc.z = fmaf(b0.x, w0, acc.z); acc.w = fmaf(b0.y, w0, acc.w);
            float2 a1 = __half22float2(*(const __half2*)&r1.x);
            float2 b1 = __half22float2(*(const __half2*)&r1.y);
            acc.x = fmaf(a1.x, w1, acc.x); acc.y = fmaf(a1.y, w1, acc.y);
            acc.z = fmaf(b1.x, w1, acc.z); acc.w = fmaf(b1.y, w1, acc.w);
            float2 a2 = __half22float2(*(const __half2*)&r2.x);
            float2 b2 = __half22float2(*(const __half2*)&r2.y);
            acc.x = fmaf(a2.x, w2, acc.x); acc.y = fmaf(a2.y, w2, acc.y);
            acc.z = fmaf(b2.x, w2, acc.z); acc.w = fmaf(b2.y, w2, acc.w);
            float2 a3 = __half22float2(*(const __half2*)&r3.x);
            float2 b3 = __half22float2(*(const __half2*)&r3.y);
            acc.x = fmaf(a3.x, w3, acc.x); acc.y = fmaf(a3.y, w3, acc.y);
            acc.z = fmaf(b3.x, w3, acc.z); acc.w = fmaf(b3.y, w3, acc.w);
        }
        for (; t < cnt; t++) {
            int   cc = __shfl_sync(0xffffffffu, c,  t);
            float ww = __shfl_sync(0xffffffffu, sw, t);
            uint2 raw = *(const uint2*)(xh + (size_t)cc * DH + lane * 4);
            float2 v01 = __half22float2(*(const __half2*)&raw.x);
            float2 v23 = __half22float2(*(const __half2*)&raw.y);
            acc.x = fmaf(v01.x, ww, acc.x);
            acc.y = fmaf(v01.y, ww, acc.y);
            acc.z = fmaf(v23.x, ww, acc.z);
            acc.w = fmaf(v23.y, ww, acc.w);
        }
    }
    float ri = g_rs_in[w] * (1.0f - ALPHA_C);
    float4 xv = *(const float4*)(x0 + (size_t)w * DH + lane * 4);
    float4 o;
    o.x = fmaf(acc.x, ri, ALPHA_C * xv.x);
    o.y = fmaf(acc.y, ri, ALPHA_C * xv.y);
    o.z = fmaf(acc.z, ri, ALPHA_C * xv.z);
    o.w = fmaf(acc.w, ri, ALPHA_C * xv.w);
    *(float4*)(f + (size_t)w * DH + lane * 4) = o;
}

// ---------------- persistent tensor-core GEMM (3xBF16, 32x32 warp tiles) ----------------
// C[n,NW] = A[n,128] @ B[128,NW] + bias, NW in {128,64}
// Block tile 64 x NW (full width). 8 warps: wm=warp&1 (2 m-halves of 32 rows),
// wn=warp>>1 (4 n-quarters of NW/4 cols). Warp tile 32 x NW/4 = 2 m16 x NT n8.
// B staged+split once per persistent block; A per M tile. All frag loads ldsm.x4.
// WMODE: 0 = fp32 C only; 1 = fp32 + fp16; 2 = fp16 only
template <int NW, bool RELU, int WMODE>
__global__ void __launch_bounds__(256) gemm_tc_kernel(const float* __restrict__ A,
                                                      const float* __restrict__ B,
                                                      const float* __restrict__ bias,
                                                      float* __restrict__ C,
                                                      __half* __restrict__ C16, int n) {
    constexpr int AW = 68;               // u32 stride per A row
    constexpr int BW = 68;               // u32 stride per B col
    constexpr int NT = NW / 32;          // n8-tiles per warp (4 or 2)
    extern __shared__ uint32_t smu[];
    uint32_t* Ahi = smu;                 // 64 x 68
    uint32_t* Alo = Ahi + 64 * AW;
    uint32_t* Bhi = Alo + 64 * AW;       // NW cols x 68 ([col][kword])
    uint32_t* Blo = Bhi + NW * BW;

    int tid = threadIdx.x;

    // ---- stage + split B (128 k x NW n) once, stored [col][k] ----
    {
        __nv_bfloat16* BhiH = (__nv_bfloat16*)Bhi;
        __nv_bfloat16* BloH = (__nv_bfloat16*)Blo;
#pragma unroll
        for (int i = 0; i < NW / 2; i++) {
            int idx = tid + i * 256;       // 0 .. 128*NW-1
            int k   = idx / NW;
            int col = idx % NW;
            float v = B[(size_t)k * NW + col];
            __nv_bfloat16 h, l;
            bf16_split(v, h, l);
            BhiH[col * (BW * 2) + k] = h;
            BloH[col * (BW * 2) + k] = l;
        }
    }

    int warp = tid >> 5, lane = tid & 31;
    int gid  = lane >> 2, tig = lane & 3;
    int wm   = warp & 1;                 // 2 m-halves of 32 rows
    int wn   = warp >> 1;                // 4 n-quarters

    // A ldsm.x4 offsets per m16-group: matrices [m0-7,k0-7][m8-15,k0-7][m0-7,k8-15][m8-15,k8-15]
    int a_row = (lane & 7) + ((lane >> 3) & 1) * 8;   // + wm*32 + mt*16
    int a_kx  = (lane >> 4) * 4;
    // B ldsm.x4: lanes 0-15 -> n8 tile 2p (b0,b1), lanes 16-31 -> tile 2p+1
    int b_col = wn * (NW / 4) + (lane & 7) + ((lane >> 4) & 1) * 8;
    int b_kx  = ((lane >> 3) & 1) * 4;
    uint32_t b_off = (uint32_t)(b_col * BW + b_kx) * 4u;

    uint32_t sAhi = (uint32_t)__cvta_generic_to_shared(Ahi);
    uint32_t sAlo = (uint32_t)__cvta_generic_to_shared(Alo);
    uint32_t sBhi = (uint32_t)__cvta_generic_to_shared(Bhi);
    uint32_t sBlo = (uint32_t)__cvta_generic_to_shared(Blo);

    const float4* A4 = (const float4*)A;

    for (int mb = blockIdx.x; mb * 64 < n; mb += gridDim.x) {
        int m0 = mb * 64;
        __syncthreads();   // prev compute done (and B stage on first iter)
        // ---- stage + split A tile (64 x 128) ----
        {
            size_t base4 = (size_t)m0 * (DH / 4);
#pragma unroll
            for (int i = 0; i < 8; i++) {
                int idx = tid + i * 256;
                int row = idx >> 5;
                int c4  = idx & 31;
                float4 v = (m0 + row < n) ? A4[base4 + idx] : make_float4(0.f, 0.f, 0.f, 0.f);
                __nv_bfloat16 hx, lx, hy, ly, hz, lz, hw, lw;
                bf16_split(v.x, hx, lx); bf16_split(v.y, hy, ly);
                bf16_split(v.z, hz, lz); bf16_split(v.w, hw, lw);
                Ahi[row * AW + c4 * 2]     = pack_bf2(hx, hy);
                Ahi[row * AW + c4 * 2 + 1] = pack_bf2(hz, hw);
                Alo[row * AW + c4 * 2]     = pack_bf2(lx, ly);
                Alo[row * AW + c4 * 2 + 1] = pack_bf2(lz, lw);
            }
        }
        __syncthreads();

        float acc[2][NT][4];
#pragma unroll
        for (int mt = 0; mt < 2; mt++)
#pragma unroll
            for (int nt = 0; nt < NT; nt++)
#pragma unroll
                for (int q = 0; q < 4; q++) acc[mt][nt][q] = 0.f;

#pragma unroll
        for (int k0 = 0; k0 < DH; k0 += 16) {
            uint32_t kb = (uint32_t)(k0 >> 1) * 4u;
            uint32_t ah[2][4], al[2][4];
#pragma unroll
            for (int mt = 0; mt < 2; mt++) {
                uint32_t ao = (uint32_t)((wm * 32 + mt * 16 + a_row) * AW + a_kx) * 4u + kb;
                ldsm_x4(sAhi + ao, ah[mt]);
                ldsm_x4(sAlo + ao, al[mt]);
            }
#pragma unroll
            for (int p = 0; p < NT / 2; p++) {
                uint32_t bo = b_off + (uint32_t)(p * 16 * BW) * 4u + kb;
                uint32_t bh[4], bl[4];
                ldsm_x4(sBhi + bo, bh);
                ldsm_x4(sBlo + bo, bl);
#pragma unroll
                for (int mt = 0; mt < 2; mt++) {
                    mma16(acc[mt][2 * p],     ah[mt], bh[0], bh[1]);
                    mma16(acc[mt][2 * p],     ah[mt], bl[0], bl[1]);
                    mma16(acc[mt][2 * p],     al[mt], bh[0], bh[1]);
                    mma16(acc[mt][2 * p + 1], ah[mt], bh[2], bh[3]);
                    mma16(acc[mt][2 * p + 1], ah[mt], bl[2], bl[3]);
                    mma16(acc[mt][2 * p + 1], al[mt], bh[2], bh[3]);
                }
            }
        }

        // ---- epilogue ----
#pragma unroll
        for (int mt = 0; mt < 2; mt++) {
            int r0 = m0 + wm * 32 + mt * 16 + gid;
            int r1 = r0 + 8;
#pragma unroll
            for (int nt = 0; nt < NT; nt++) {
                int nc0 = wn * (NW / 4) + nt * 8 + tig * 2;
                float bv0 = bias[nc0], bv1 = bias[nc0 + 1];
                float v0 = acc[mt][nt][0] + bv0;
                float v1 = acc[mt][nt][1] + bv1;
                float v2 = acc[mt][nt][2] + bv0;
                float v3 = acc[mt][nt][3] + bv1;
                if (RELU) {
                    v0 = fmaxf(v0, 0.f); v1 = fmaxf(v1, 0.f);
                    v2 = fmaxf(v2, 0.f); v3 = fmaxf(v3, 0.f);
                }
                if (r0 < n) {
                    if (WMODE != 2) *(float2*)&C[(size_t)r0 * NW + nc0] = make_float2(v0, v1);
                    if (WMODE != 0) *(__half2*)&C16[(size_t)r0 * NW + nc0] = __floats2half2_rn(v0, v1);
                }
                if (r1 < n) {
                    if (WMODE != 2) *(float2*)&C[(size_t)r1 * NW + nc0] = make_float2(v2, v3);
                    if (WMODE != 0) *(__half2*)&C16[(size_t)r1 * NW + nc0] = __floats2half2_rn(v2, v3);
                }
            }
        }
    }
}

// ---------------- launch ----------------
extern "C" void kernel_launch(void* const* d_in, const int* in_sizes, int n_in,
                              void* d_out, int out_size) {
    const float* feat = (const float*)d_in[0];
    const int*   src  = (const int*)  d_in[1];
    const int*   dst  = (const int*)  d_in[2];
    const float* w1   = (const float*)d_in[3];
    const float* b1   = (const float*)d_in[4];
    const float* cw1  = (const float*)d_in[5];
    const float* cb1  = (const float*)d_in[6];
    const float* cw2  = (const float*)d_in[7];
    const float* cb2  = (const float*)d_in[8];
    const float* w2   = (const float*)d_in[9];
    const float* b2   = (const float*)d_in[10];
    float* out = (float*)d_out;

    int n = in_sizes[0] / DH;   // 100000
    int E = in_sizes[1];        // 1600000

    void *p_h0, *p_xh, *p_f, *p_wp1, *p_wf, *p_bf;
    cudaGetSymbolAddress(&p_h0,  g_h0);
    cudaGetSymbolAddress(&p_xh,  g_xh);
    cudaGetSymbolAddress(&p_f,   g_f);
    cudaGetSymbolAddress(&p_wp1, g_wp1);
    cudaGetSymbolAddress(&p_wf,  g_wf);
    cudaGetSymbolAddress(&p_bf,  g_bf);

    // smem: A 2x64x68 u32 + B 2xNWx68 u32
    constexpr int SMEM128 = (2 * 64 * 68 + 2 * 128 * 68) * 4;  // 104448 -> 2 blocks/SM
    constexpr int SMEM64  = (2 * 64 * 68 + 2 * 64 * 68) * 4;   // 69632  -> 3 blocks/SM
    cudaFuncSetAttribute(gemm_tc_kernel<128, true, 1>,
                         cudaFuncAttributeMaxDynamicSharedMemorySize, SMEM128);
    cudaFuncSetAttribute(gemm_tc_kernel<128, true, 2>,
                         cudaFuncAttributeMaxDynamicSharedMemorySize, SMEM128);
    cudaFuncSetAttribute(gemm_tc_kernel<64, false, 0>,
                         cudaFuncAttributeMaxDynamicSharedMemorySize, SMEM64);

    int nb   = (n + 255) / 256;
    int eb   = (E + 255) / 256;
    int sb   = (n * 32 + 255) / 256;
    int nblk = (n + 255) / 256;
    const int PG2 = 296;   // 2 blocks/SM persistent grid
    const int PG3 = 444;   // 3 blocks/SM

    prep_weights_kernel<<<DH, DH>>>(cw1, cw2, w2, cb2, b2);
    zero_deg_kernel<<<nb, 256>>>(n);
    deg_kernel<<<eb, 256>>>(src, dst, E);

    // 4: fc1 -> h0 (fp32) + xh (fp16) — ncu capture lands here
    gemm_tc_kernel<128, true, 1><<<PG2, 256, SMEM128>>>(feat, w1, b1,
        (float*)p_h0, (__half*)p_xh, n);

    rs_blocksum_kernel<<<nblk, 256>>>(n);
    scan_sums_kernel<<<1, 512>>>(nblk, n);
    writeptr_kernel<<<nblk, 256>>>(n);
    fill_kernel<<<eb, 256>>>(src, dst, E);

    spmm_kernel<<<sb, 256>>>((const __half*)p_xh, (const float*)p_h0, (float*)p_f, n);

    gemm_tc_kernel<128, true, 2><<<PG2, 256, SMEM128>>>((const float*)p_f, (const float*)p_wp1,
        cb1, (float*)nullptr, (__half*)p_xh, n);

    spmm_kernel<<<sb, 256>>>((const __half*)p_xh, (const float*)p_h0, (float*)p_f, n);

    gemm_tc_kernel<64, false, 0><<<PG3, 256, SMEM64>>>((const float*)p_f, (const float*)p_wf,
        (const float*)p_bf, out, (__half*)nullptr, n);
}